// round 2
// baseline (speedup 1.0000x reference)
#include <cuda_runtime.h>
#include <math.h>

#define NN 50000
#define NE 800000
#define ET (NN + NE)   // edges + self loops = 850000
#define NB 512
#define ND 256
#define NH 4
#define HC 64

// ---------------- static device scratch (no allocs allowed) ----------------
__device__ float g_x[(size_t)NN * ND];      // layer activations (post-ELU)
__device__ float g_h[(size_t)NN * ND];      // x @ W
__device__ float g_asrc[NN * NH];
__device__ float g_adst[NN * NH];
__device__ float g_alpha[(size_t)NH * ET];  // leaky-relu'd logits, CSR order, per-head planes
__device__ int   g_counts[NN + 1];
__device__ int   g_off[NN + 1];
__device__ int   g_cur[NN + 1];
__device__ int   g_srcs[ET];
__device__ int   g_dsts[ET];
__device__ float g_he[NB * ND];
__device__ float g_te[NB * ND];

// ---------------- CSR construction ----------------
__global__ void k_init_counts() {
    int i = blockIdx.x * blockDim.x + threadIdx.x;
    if (i < NN) g_counts[i] = 1;   // self-loop pre-counted
}

__global__ void k_count(const int* __restrict__ ei) {
    int e = blockIdx.x * blockDim.x + threadIdx.x;
    if (e < NE) atomicAdd(&g_counts[ei[NE + e]], 1);
}

// single-block exclusive scan over g_counts[0..NN) -> g_off[0..NN]
__global__ void k_scan() {
    __shared__ int sh[1024];
    __shared__ int carry;
    int tid = threadIdx.x;
    if (tid == 0) carry = 0;
    __syncthreads();
    for (int base = 0; base < NN; base += 1024) {
        int i = base + tid;
        int v = (i < NN) ? g_counts[i] : 0;
        sh[tid] = v;
        __syncthreads();
        for (int o = 1; o < 1024; o <<= 1) {
            int t = (tid >= o) ? sh[tid - o] : 0;
            __syncthreads();
            sh[tid] += t;
            __syncthreads();
        }
        if (i < NN) g_off[i] = carry + sh[tid] - v;
        __syncthreads();
        if (tid == 1023) carry += sh[1023];
        __syncthreads();
    }
    if (tid == 0) g_off[NN] = carry;
}

__global__ void k_copycur() {
    int i = blockIdx.x * blockDim.x + threadIdx.x;
    if (i < NN) g_cur[i] = g_off[i];
}

__global__ void k_scatter(const int* __restrict__ ei) {
    int e = blockIdx.x * blockDim.x + threadIdx.x;
    if (e >= NE) return;
    int s = ei[e], d = ei[NE + e];
    int p = atomicAdd(&g_cur[d], 1);
    g_srcs[p] = s;
    g_dsts[p] = d;
}

__global__ void k_selfloops() {
    int i = blockIdx.x * blockDim.x + threadIdx.x;
    if (i >= NN) return;
    int p = atomicAdd(&g_cur[i], 1);
    g_srcs[p] = i;
    g_dsts[p] = i;
}

// ---------------- SGEMM: h = x @ W   (M=NN, N=256, K=256) ----------------
__global__ void __launch_bounds__(256) k_sgemm(const float* __restrict__ xext, int useg,
                                               const float* __restrict__ W) {
    const float* A = useg ? g_x : xext;
    __shared__ float As[8][128];
    __shared__ float Bs[8][128];
    int tid = threadIdx.x;
    int bx = blockIdx.x, by = blockIdx.y;
    int tx = tid & 15, ty = tid >> 4;
    int aRow = tid >> 1, aCol = (tid & 1) * 4;
    int bRow = tid >> 5, bCol = (tid & 31) * 4;
    int mBase = by * 128;
    float acc[8][8] = {};
    const float* Ab = A + (size_t)mBase * ND;
    const float* Bb = W + bx * 128;
    for (int k0 = 0; k0 < ND; k0 += 8) {
        float4 av = make_float4(0.f, 0.f, 0.f, 0.f);
        if (mBase + aRow < NN) av = *(const float4*)(Ab + (size_t)aRow * ND + k0 + aCol);
        As[aCol + 0][aRow] = av.x;
        As[aCol + 1][aRow] = av.y;
        As[aCol + 2][aRow] = av.z;
        As[aCol + 3][aRow] = av.w;
        *(float4*)&Bs[bRow][bCol] = *(const float4*)(Bb + (size_t)(k0 + bRow) * ND + bCol);
        __syncthreads();
#pragma unroll
        for (int k = 0; k < 8; k++) {
            float4 a0 = *(float4*)&As[k][ty * 8];
            float4 a1 = *(float4*)&As[k][ty * 8 + 4];
            float4 b0 = *(float4*)&Bs[k][tx * 8];
            float4 b1 = *(float4*)&Bs[k][tx * 8 + 4];
            float ar[8] = {a0.x, a0.y, a0.z, a0.w, a1.x, a1.y, a1.z, a1.w};
            float br[8] = {b0.x, b0.y, b0.z, b0.w, b1.x, b1.y, b1.z, b1.w};
#pragma unroll
            for (int i = 0; i < 8; i++)
#pragma unroll
                for (int j = 0; j < 8; j++) acc[i][j] += ar[i] * br[j];
        }
        __syncthreads();
    }
#pragma unroll
    for (int i = 0; i < 8; i++) {
        int m = mBase + ty * 8 + i;
        if (m >= NN) continue;
        float* Cr = g_h + (size_t)m * ND + bx * 128 + tx * 8;
        *(float4*)Cr = make_float4(acc[i][0], acc[i][1], acc[i][2], acc[i][3]);
        *(float4*)(Cr + 4) = make_float4(acc[i][4], acc[i][5], acc[i][6], acc[i][7]);
    }
}

// ---------------- per-node attention scores: asrc/adst = einsum(h, a) ----------------
__global__ void k_att(const float* __restrict__ a_s, const float* __restrict__ a_d) {
    int gw = (blockIdx.x * blockDim.x + threadIdx.x) >> 5;
    int lane = threadIdx.x & 31;
    if (gw >= NN) return;
    const float* row = g_h + (size_t)gw * ND;
    float ps[4] = {0.f, 0.f, 0.f, 0.f}, pd[4] = {0.f, 0.f, 0.f, 0.f};
#pragma unroll
    for (int i = 0; i < 8; i++) {
        int c = i * 32 + lane;
        float v = row[c];
        ps[i >> 1] += v * a_s[c];
        pd[i >> 1] += v * a_d[c];
    }
#pragma unroll
    for (int hh = 0; hh < 4; hh++) {
        float v = ps[hh], w = pd[hh];
#pragma unroll
        for (int o = 16; o; o >>= 1) {
            v += __shfl_xor_sync(0xffffffffu, v, o);
            w += __shfl_xor_sync(0xffffffffu, w, o);
        }
        if (lane == 0) {
            g_asrc[gw * 4 + hh] = v;
            g_adst[gw * 4 + hh] = w;
        }
    }
}

// ---------------- per sorted edge: alpha = leaky(asrc[s] + adst[d]) ----------------
__global__ void k_alpha() {
    int e = blockIdx.x * blockDim.x + threadIdx.x;
    if (e >= ET) return;
    int s = g_srcs[e], d = g_dsts[e];
    float4 as = *(const float4*)&g_asrc[s * 4];
    float4 ad = *(const float4*)&g_adst[d * 4];
    float v;
    v = as.x + ad.x; g_alpha[0 * (size_t)ET + e] = v > 0.f ? v : 0.2f * v;
    v = as.y + ad.y; g_alpha[1 * (size_t)ET + e] = v > 0.f ? v : 0.2f * v;
    v = as.z + ad.z; g_alpha[2 * (size_t)ET + e] = v > 0.f ? v : 0.2f * v;
    v = as.w + ad.w; g_alpha[3 * (size_t)ET + e] = v > 0.f ? v : 0.2f * v;
}

// ---------------- aggregation: segment softmax + weighted sum + bias + ELU ----------------
// one warp per (node, head); block = 2 nodes x 4 heads = 8 warps
__global__ void __launch_bounds__(256) k_agg(const float* __restrict__ bias) {
    int warp = threadIdx.x >> 5;
    int lane = threadIdx.x & 31;
    int node = blockIdx.x * 2 + (warp >> 2);
    int head = warp & 3;
    if (node >= NN) return;
    int beg = g_off[node], end = g_off[node + 1];
    const float* al = g_alpha + (size_t)head * ET;

    // pass 1: segment max
    float m = -1e30f;
    for (int i = beg + lane; i < end; i += 32) m = fmaxf(m, al[i]);
#pragma unroll
    for (int o = 16; o; o >>= 1) m = fmaxf(m, __shfl_xor_sync(0xffffffffu, m, o));

    // pass 2: exp-sum and weighted feature accumulation (broadcast via shfl)
    int cbase = head * HC + lane;
    float denom = 0.f, acc0 = 0.f, acc1 = 0.f;
    for (int base = beg; base < end; base += 32) {
        int i = base + lane;
        float ea = 0.f;
        int s = 0;
        if (i < end) {
            ea = __expf(al[i] - m);
            s = g_srcs[i];
        }
        denom += ea;
        int cnt = min(32, end - base);
        for (int j = 0; j < cnt; j++) {
            float eaj = __shfl_sync(0xffffffffu, ea, j);
            int sj = __shfl_sync(0xffffffffu, s, j);
            const float* hr = g_h + (size_t)sj * ND + cbase;
            acc0 += eaj * hr[0];
            acc1 += eaj * hr[32];
        }
    }
#pragma unroll
    for (int o = 16; o; o >>= 1) denom += __shfl_xor_sync(0xffffffffu, denom, o);

    float inv = 1.0f / denom;
    float v0 = acc0 * inv + bias[cbase];
    float v1 = acc1 * inv + bias[cbase + 32];
    v0 = v0 > 0.f ? v0 : expm1f(v0);
    v1 = v1 > 0.f ? v1 : expm1f(v1);
    g_x[(size_t)node * ND + cbase] = v0;
    g_x[(size_t)node * ND + cbase + 32] = v1;
}

// ---------------- pooling: segment_sum over sorted batch ----------------
__global__ void k_pool(const int* __restrict__ batch, int which) {
    __shared__ int sb, se;
    int b = blockIdx.x;
    if (threadIdx.x == 0) {
        int lo = 0, hi = NN;
        while (lo < hi) { int mid = (lo + hi) >> 1; if (batch[mid] < b) lo = mid + 1; else hi = mid; }
        sb = lo;
        lo = 0; hi = NN;
        while (lo < hi) { int mid = (lo + hi) >> 1; if (batch[mid] < b + 1) lo = mid + 1; else hi = mid; }
        se = lo;
    }
    __syncthreads();
    int c = threadIdx.x;
    float acc = 0.f;
    for (int i = sb; i < se; i++) acc += g_x[(size_t)i * ND + c];
    (which ? g_te : g_he)[b * ND + c] = acc;
}

// ---------------- final MLP ----------------
__global__ void k_mlp(const int* __restrict__ rel, const float* __restrict__ kge,
                      const float* __restrict__ W1, const float* __restrict__ b1,
                      const float* __restrict__ W2, const float* __restrict__ b2,
                      float* __restrict__ out) {
    int b = blockIdx.x;   // 512
    int j = threadIdx.x;  // 64
    __shared__ float zin[2 * ND + HC];
    for (int k = j; k < ND; k += 64) zin[k] = g_he[b * ND + k];
    for (int k = j; k < ND; k += 64) zin[ND + k] = g_te[b * ND + k];
    int r = rel[b];
    zin[2 * ND + j] = kge[r * HC + j];
    __syncthreads();
    float z = b1[j];
    for (int k = 0; k < 2 * ND + HC; k++) z += zin[k] * W1[k * 64 + j];
    z = fmaxf(z, 0.f);
    __shared__ float zs[64];
    zs[j] = z * W2[j];
    __syncthreads();
    if (j < 32) {
        float v = zs[j] + zs[j + 32];
#pragma unroll
        for (int o = 16; o; o >>= 1) v += __shfl_xor_sync(0xffffffffu, v, o);
        if (j == 0) out[b] = v + b2[0];
    }
}

// ---------------- launcher ----------------
extern "C" void kernel_launch(void* const* d_in, const int* in_sizes, int n_in,
                              void* d_out, int out_size) {
    const float* head_x    = (const float*)d_in[0];
    const int*   head_ei   = (const int*)d_in[1];
    const int*   head_b    = (const int*)d_in[2];
    const float* tail_x    = (const float*)d_in[3];
    const int*   tail_ei   = (const int*)d_in[4];
    const int*   tail_b    = (const int*)d_in[5];
    const int*   rel       = (const int*)d_in[6];
    const float* Ws        = (const float*)d_in[7];
    const float* att_src   = (const float*)d_in[8];
    const float* att_dst   = (const float*)d_in[9];
    const float* biases    = (const float*)d_in[10];
    const float* kge       = (const float*)d_in[11];
    const float* W1        = (const float*)d_in[12];
    const float* b1        = (const float*)d_in[13];
    const float* W2        = (const float*)d_in[14];
    const float* b2        = (const float*)d_in[15];
    float*       out       = (float*)d_out;

    const int TB = 256;
    for (int enc = 0; enc < 2; enc++) {
        const float* x0   = enc ? tail_x : head_x;
        const int*   ei   = enc ? tail_ei : head_ei;
        const int*   bat  = enc ? tail_b : head_b;

        k_init_counts<<<(NN + TB - 1) / TB, TB>>>();
        k_count<<<(NE + TB - 1) / TB, TB>>>(ei);
        k_scan<<<1, 1024>>>();
        k_copycur<<<(NN + TB - 1) / TB, TB>>>();
        k_scatter<<<(NE + TB - 1) / TB, TB>>>(ei);
        k_selfloops<<<(NN + TB - 1) / TB, TB>>>();

        for (int l = 0; l < 3; l++) {
            k_sgemm<<<dim3(2, (NN + 127) / 128), 256>>>(x0, l > 0, Ws + (size_t)l * ND * ND);
            k_att<<<(NN * 32 + TB - 1) / TB, TB>>>(att_src + l * ND, att_dst + l * ND);
            k_alpha<<<(ET + TB - 1) / TB, TB>>>();
            k_agg<<<(NN + 1) / 2, 256>>>(biases + l * ND);
        }
        k_pool<<<NB, ND>>>(bat, enc);
    }
    k_mlp<<<NB, 64>>>(rel, kge, W1, b1, W2, b2, out);
}

// round 3
// speedup vs baseline: 1.3255x; 1.3255x over previous
#include <cuda_runtime.h>
#include <cuda_bf16.h>
#include <math.h>

#define NN 50000
#define NE 800000
#define ET (NN + NE)   // edges + self loops = 850000
#define NB 512
#define ND 256
#define NH 4
#define HC 64

// ---------------- static device scratch ----------------
__device__ float g_x[(size_t)NN * ND];            // final-layer activations (for pooling)
__device__ __nv_bfloat16 g_xhi[(size_t)NN * ND];  // activation hi part (GEMM A input)
__device__ __nv_bfloat16 g_xlo[(size_t)NN * ND];  // activation lo part
__device__ __nv_bfloat16 g_whi[3 * ND * ND];      // weights hi, TRANSPOSED [l][n][k]
__device__ __nv_bfloat16 g_wlo[3 * ND * ND];
__device__ float g_h[(size_t)NN * ND];            // x @ W (fp32)
__device__ float g_asrc[NN * NH];
__device__ float g_adst[NN * NH];
__device__ float g_alpha[(size_t)NH * ET];
__device__ int   g_counts[NN + 1];
__device__ int   g_off[NN + 1];
__device__ int   g_cur[NN + 1];
__device__ int   g_srcs[ET];
__device__ int   g_dsts[ET];
__device__ float g_he[NB * ND];
__device__ float g_te[NB * ND];

// ---------------- fp32 -> bf16 hi/lo split helpers ----------------
__device__ __forceinline__ void split_bf16(float v, __nv_bfloat16& hi, __nv_bfloat16& lo) {
    hi = __float2bfloat16(v);
    lo = __float2bfloat16(v - __bfloat162float(hi));
}

__global__ void k_split_x(const float* __restrict__ x) {
    int i = blockIdx.x * blockDim.x + threadIdx.x;
    int stride = gridDim.x * blockDim.x;
    for (; i < NN * ND; i += stride) {
        __nv_bfloat16 hi, lo;
        split_bf16(x[i], hi, lo);
        g_xhi[i] = hi;
        g_xlo[i] = lo;
    }
}

// weights: transpose to [l][n][k] so GEMM B-tile rows are n with k contiguous
__global__ void k_split_w(const float* __restrict__ Ws) {
    int i = blockIdx.x * blockDim.x + threadIdx.x;
    if (i >= 3 * ND * ND) return;
    int l = i / (ND * ND);
    int r = i % (ND * ND);
    int n = r / ND;
    int k = r % ND;
    float v = Ws[l * ND * ND + k * ND + n];
    __nv_bfloat16 hi, lo;
    split_bf16(v, hi, lo);
    g_whi[i] = hi;
    g_wlo[i] = lo;
}

// ---------------- CSR construction ----------------
__global__ void k_init_counts() {
    int i = blockIdx.x * blockDim.x + threadIdx.x;
    if (i < NN) g_counts[i] = 1;
}

__global__ void k_count(const int* __restrict__ ei) {
    int e = blockIdx.x * blockDim.x + threadIdx.x;
    if (e < NE) atomicAdd(&g_counts[ei[NE + e]], 1);
}

__global__ void k_scan() {
    __shared__ int sh[1024];
    __shared__ int carry;
    int tid = threadIdx.x;
    if (tid == 0) carry = 0;
    __syncthreads();
    for (int base = 0; base < NN; base += 1024) {
        int i = base + tid;
        int v = (i < NN) ? g_counts[i] : 0;
        sh[tid] = v;
        __syncthreads();
        for (int o = 1; o < 1024; o <<= 1) {
            int t = (tid >= o) ? sh[tid - o] : 0;
            __syncthreads();
            sh[tid] += t;
            __syncthreads();
        }
        if (i < NN) g_off[i] = carry + sh[tid] - v;
        __syncthreads();
        if (tid == 1023) carry += sh[1023];
        __syncthreads();
    }
    if (tid == 0) g_off[NN] = carry;
}

__global__ void k_copycur() {
    int i = blockIdx.x * blockDim.x + threadIdx.x;
    if (i < NN) g_cur[i] = g_off[i];
}

__global__ void k_scatter(const int* __restrict__ ei) {
    int e = blockIdx.x * blockDim.x + threadIdx.x;
    if (e >= NE) return;
    int s = ei[e], d = ei[NE + e];
    int p = atomicAdd(&g_cur[d], 1);
    g_srcs[p] = s;
    g_dsts[p] = d;
}

__global__ void k_selfloops() {
    int i = blockIdx.x * blockDim.x + threadIdx.x;
    if (i >= NN) return;
    int p = atomicAdd(&g_cur[i], 1);
    g_srcs[p] = i;
    g_dsts[p] = i;
}

// ---------------- bf16x3 tensor-core GEMM: g_h = (xhi+xlo) @ W  ----------------
// block = 128x128 tile, 8 warps (2x4), warp tile 64x32; K=256, BK=32
__device__ __forceinline__ void mma16816(float* c, const unsigned* a, const unsigned* b) {
    asm volatile(
        "mma.sync.aligned.m16n8k16.row.col.f32.bf16.bf16.f32 "
        "{%0,%1,%2,%3},{%4,%5,%6,%7},{%8,%9},{%0,%1,%2,%3};"
        : "+f"(c[0]), "+f"(c[1]), "+f"(c[2]), "+f"(c[3])
        : "r"(a[0]), "r"(a[1]), "r"(a[2]), "r"(a[3]), "r"(b[0]), "r"(b[1]));
}

#define LDP 40   // smem row pitch (bf16 elems): bank stride 20 -> conflict-free frags

__global__ void __launch_bounds__(256, 2) k_gemm(const __nv_bfloat16* __restrict__ whi,
                                                 const __nv_bfloat16* __restrict__ wlo) {
    __shared__ __nv_bfloat16 Ah[128][LDP], Al[128][LDP], Bh[128][LDP], Bl[128][LDP];
    int tid = threadIdx.x;
    int mBase = blockIdx.y * 128, nBase = blockIdx.x * 128;
    int w = tid >> 5, lane = tid & 31;
    int wm = w >> 2, wn = w & 3;
    int g = lane >> 2, thr = lane & 3;
    float c[4][4][4];
#pragma unroll
    for (int a = 0; a < 4; a++)
#pragma unroll
        for (int b = 0; b < 4; b++)
#pragma unroll
            for (int d = 0; d < 4; d++) c[a][b][d] = 0.f;

    for (int k0 = 0; k0 < ND; k0 += 32) {
#pragma unroll
        for (int j = 0; j < 4; j++) {
            int idx = tid + 256 * j;
            int row = idx >> 3, ch = idx & 7;     // 8 uint2-chunks of 4 bf16 per 32-col row
            int rg = mBase + row;
            uint2 vh = make_uint2(0u, 0u), vl = make_uint2(0u, 0u);
            if (rg < NN) {
                size_t off = (size_t)rg * ND + k0 + ch * 4;
                vh = *(const uint2*)(g_xhi + off);
                vl = *(const uint2*)(g_xlo + off);
            }
            *(uint2*)&Ah[row][ch * 4] = vh;
            *(uint2*)&Al[row][ch * 4] = vl;
            size_t boff = (size_t)(nBase + row) * ND + k0 + ch * 4;
            *(uint2*)&Bh[row][ch * 4] = *(const uint2*)(whi + boff);
            *(uint2*)&Bl[row][ch * 4] = *(const uint2*)(wlo + boff);
        }
        __syncthreads();
#pragma unroll
        for (int kk = 0; kk < 32; kk += 16) {
            unsigned bhf[4][2], blf[4][2];
#pragma unroll
            for (int ni = 0; ni < 4; ni++) {
                int nr = wn * 32 + ni * 8 + g;
                bhf[ni][0] = *(const unsigned*)&Bh[nr][kk + thr * 2];
                bhf[ni][1] = *(const unsigned*)&Bh[nr][kk + thr * 2 + 8];
                blf[ni][0] = *(const unsigned*)&Bl[nr][kk + thr * 2];
                blf[ni][1] = *(const unsigned*)&Bl[nr][kk + thr * 2 + 8];
            }
#pragma unroll
            for (int mi = 0; mi < 4; mi++) {
                int r0 = wm * 64 + mi * 16 + g;
                unsigned ahf[4], alf[4];
                ahf[0] = *(const unsigned*)&Ah[r0][kk + thr * 2];
                ahf[1] = *(const unsigned*)&Ah[r0 + 8][kk + thr * 2];
                ahf[2] = *(const unsigned*)&Ah[r0][kk + thr * 2 + 8];
                ahf[3] = *(const unsigned*)&Ah[r0 + 8][kk + thr * 2 + 8];
                alf[0] = *(const unsigned*)&Al[r0][kk + thr * 2];
                alf[1] = *(const unsigned*)&Al[r0 + 8][kk + thr * 2];
                alf[2] = *(const unsigned*)&Al[r0][kk + thr * 2 + 8];
                alf[3] = *(const unsigned*)&Al[r0 + 8][kk + thr * 2 + 8];
#pragma unroll
                for (int ni = 0; ni < 4; ni++) {
                    mma16816(c[mi][ni], ahf, bhf[ni]);  // hi*hi
                    mma16816(c[mi][ni], ahf, blf[ni]);  // hi*lo
                    mma16816(c[mi][ni], alf, bhf[ni]);  // lo*hi
                }
            }
        }
        __syncthreads();
    }
#pragma unroll
    for (int mi = 0; mi < 4; mi++) {
        int row0 = mBase + wm * 64 + mi * 16 + g;
#pragma unroll
        for (int ni = 0; ni < 4; ni++) {
            int col = nBase + wn * 32 + ni * 8 + thr * 2;
            if (row0 < NN)
                *(float2*)&g_h[(size_t)row0 * ND + col] = make_float2(c[mi][ni][0], c[mi][ni][1]);
            if (row0 + 8 < NN)
                *(float2*)&g_h[(size_t)(row0 + 8) * ND + col] = make_float2(c[mi][ni][2], c[mi][ni][3]);
        }
    }
}

// ---------------- per-node attention scores ----------------
__global__ void k_att(const float* __restrict__ a_s, const float* __restrict__ a_d) {
    int gw = (blockIdx.x * blockDim.x + threadIdx.x) >> 5;
    int lane = threadIdx.x & 31;
    if (gw >= NN) return;
    const float* row = g_h + (size_t)gw * ND;
    float ps[4] = {0.f, 0.f, 0.f, 0.f}, pd[4] = {0.f, 0.f, 0.f, 0.f};
#pragma unroll
    for (int i = 0; i < 8; i++) {
        int c = i * 32 + lane;
        float v = row[c];
        ps[i >> 1] += v * a_s[c];
        pd[i >> 1] += v * a_d[c];
    }
#pragma unroll
    for (int hh = 0; hh < 4; hh++) {
        float v = ps[hh], w = pd[hh];
#pragma unroll
        for (int o = 16; o; o >>= 1) {
            v += __shfl_xor_sync(0xffffffffu, v, o);
            w += __shfl_xor_sync(0xffffffffu, w, o);
        }
        if (lane == 0) {
            g_asrc[gw * 4 + hh] = v;
            g_adst[gw * 4 + hh] = w;
        }
    }
}

// ---------------- alpha = leaky(asrc[s] + adst[d]) ----------------
__global__ void k_alpha() {
    int e = blockIdx.x * blockDim.x + threadIdx.x;
    if (e >= ET) return;
    int s = g_srcs[e], d = g_dsts[e];
    float4 as = *(const float4*)&g_asrc[s * 4];
    float4 ad = *(const float4*)&g_adst[d * 4];
    float v;
    v = as.x + ad.x; g_alpha[0 * (size_t)ET + e] = v > 0.f ? v : 0.2f * v;
    v = as.y + ad.y; g_alpha[1 * (size_t)ET + e] = v > 0.f ? v : 0.2f * v;
    v = as.z + ad.z; g_alpha[2 * (size_t)ET + e] = v > 0.f ? v : 0.2f * v;
    v = as.w + ad.w; g_alpha[3 * (size_t)ET + e] = v > 0.f ? v : 0.2f * v;
}

// ---------------- aggregation: segment softmax + weighted sum + bias + ELU ----------------
__global__ void __launch_bounds__(256) k_agg(const float* __restrict__ bias, int last) {
    int warp = threadIdx.x >> 5;
    int lane = threadIdx.x & 31;
    int node = blockIdx.x * 2 + (warp >> 2);
    int head = warp & 3;
    if (node >= NN) return;
    int beg = g_off[node], end = g_off[node + 1];
    const float* al = g_alpha + (size_t)head * ET;

    float m = -1e30f;
    for (int i = beg + lane; i < end; i += 32) m = fmaxf(m, al[i]);
#pragma unroll
    for (int o = 16; o; o >>= 1) m = fmaxf(m, __shfl_xor_sync(0xffffffffu, m, o));

    int cbase = head * HC + lane;
    float denom = 0.f, acc0 = 0.f, acc1 = 0.f;
    for (int base = beg; base < end; base += 32) {
        int i = base + lane;
        float ea = 0.f;
        int s = 0;
        if (i < end) {
            ea = __expf(al[i] - m);
            s = g_srcs[i];
        }
        denom += ea;
        int cnt = min(32, end - base);
        for (int j = 0; j < cnt; j++) {
            float eaj = __shfl_sync(0xffffffffu, ea, j);
            int sj = __shfl_sync(0xffffffffu, s, j);
            const float* hr = g_h + (size_t)sj * ND + cbase;
            acc0 += eaj * hr[0];
            acc1 += eaj * hr[32];
        }
    }
#pragma unroll
    for (int o = 16; o; o >>= 1) denom += __shfl_xor_sync(0xffffffffu, denom, o);

    float inv = 1.0f / denom;
    float v0 = acc0 * inv + bias[cbase];
    float v1 = acc1 * inv + bias[cbase + 32];
    v0 = v0 > 0.f ? v0 : expm1f(v0);
    v1 = v1 > 0.f ? v1 : expm1f(v1);

    size_t o0 = (size_t)node * ND + cbase;
    __nv_bfloat16 hi, lo;
    split_bf16(v0, hi, lo);
    g_xhi[o0] = hi; g_xlo[o0] = lo;
    split_bf16(v1, hi, lo);
    g_xhi[o0 + 32] = hi; g_xlo[o0 + 32] = lo;
    if (last) {
        g_x[o0] = v0;
        g_x[o0 + 32] = v1;
    }
}

// ---------------- pooling ----------------
__global__ void k_pool(const int* __restrict__ batch, int which) {
    __shared__ int sb, se;
    int b = blockIdx.x;
    if (threadIdx.x == 0) {
        int lo = 0, hi = NN;
        while (lo < hi) { int mid = (lo + hi) >> 1; if (batch[mid] < b) lo = mid + 1; else hi = mid; }
        sb = lo;
        lo = 0; hi = NN;
        while (lo < hi) { int mid = (lo + hi) >> 1; if (batch[mid] < b + 1) lo = mid + 1; else hi = mid; }
        se = lo;
    }
    __syncthreads();
    int c = threadIdx.x;
    float acc = 0.f;
    for (int i = sb; i < se; i++) acc += g_x[(size_t)i * ND + c];
    (which ? g_te : g_he)[b * ND + c] = acc;
}

// ---------------- final MLP ----------------
__global__ void k_mlp(const int* __restrict__ rel, const float* __restrict__ kge,
                      const float* __restrict__ W1, const float* __restrict__ b1,
                      const float* __restrict__ W2, const float* __restrict__ b2,
                      float* __restrict__ out) {
    int b = blockIdx.x;
    int j = threadIdx.x;
    __shared__ float zin[2 * ND + HC];
    for (int k = j; k < ND; k += 64) zin[k] = g_he[b * ND + k];
    for (int k = j; k < ND; k += 64) zin[ND + k] = g_te[b * ND + k];
    int r = rel[b];
    zin[2 * ND + j] = kge[r * HC + j];
    __syncthreads();
    float z = b1[j];
    for (int k = 0; k < 2 * ND + HC; k++) z += zin[k] * W1[k * 64 + j];
    z = fmaxf(z, 0.f);
    __shared__ float zs[64];
    zs[j] = z * W2[j];
    __syncthreads();
    if (j < 32) {
        float v = zs[j] + zs[j + 32];
#pragma unroll
        for (int o = 16; o; o >>= 1) v += __shfl_xor_sync(0xffffffffu, v, o);
        if (j == 0) out[b] = v + b2[0];
    }
}

// ---------------- launcher ----------------
extern "C" void kernel_launch(void* const* d_in, const int* in_sizes, int n_in,
                              void* d_out, int out_size) {
    const float* head_x    = (const float*)d_in[0];
    const int*   head_ei   = (const int*)d_in[1];
    const int*   head_b    = (const int*)d_in[2];
    const float* tail_x    = (const float*)d_in[3];
    const int*   tail_ei   = (const int*)d_in[4];
    const int*   tail_b    = (const int*)d_in[5];
    const int*   rel       = (const int*)d_in[6];
    const float* Ws        = (const float*)d_in[7];
    const float* att_src   = (const float*)d_in[8];
    const float* att_dst   = (const float*)d_in[9];
    const float* biases    = (const float*)d_in[10];
    const float* kge       = (const float*)d_in[11];
    const float* W1        = (const float*)d_in[12];
    const float* b1        = (const float*)d_in[13];
    const float* W2        = (const float*)d_in[14];
    const float* b2        = (const float*)d_in[15];
    float*       out       = (float*)d_out;

    const int TB = 256;
    k_split_w<<<(3 * ND * ND + TB - 1) / TB, TB>>>(Ws);

    // device pointers to __device__ globals are resolved at compile time inside kernels;
    // for passing slices we compute on host via symbol-less arithmetic in-kernel (layer offset).
    for (int enc = 0; enc < 2; enc++) {
        const float* x0   = enc ? tail_x : head_x;
        const int*   ei   = enc ? tail_ei : head_ei;
        const int*   bat  = enc ? tail_b : head_b;

        k_init_counts<<<(NN + TB - 1) / TB, TB>>>();
        k_count<<<(NE + TB - 1) / TB, TB>>>(ei);
        k_scan<<<1, 1024>>>();
        k_copycur<<<(NN + TB - 1) / TB, TB>>>();
        k_scatter<<<(NE + TB - 1) / TB, TB>>>(ei);
        k_selfloops<<<(NN + TB - 1) / TB, TB>>>();

        k_split_x<<<592, 256>>>(x0);

        for (int l = 0; l < 3; l++) {
            __nv_bfloat16 *whi_l, *wlo_l;
            cudaGetSymbolAddress((void**)&whi_l, g_whi);
            cudaGetSymbolAddress((void**)&wlo_l, g_wlo);
            whi_l += (size_t)l * ND * ND;
            wlo_l += (size_t)l * ND * ND;
            k_gemm<<<dim3(2, (NN + 127) / 128), 256>>>(whi_l, wlo_l);
            k_att<<<(NN * 32 + TB - 1) / TB, TB>>>(att_src + l * ND, att_dst + l * ND);
            k_alpha<<<(ET + TB - 1) / TB, TB>>>();
            k_agg<<<NN / 2, 256>>>(biases + l * ND, l == 2);
        }
        k_pool<<<NB, ND>>>(bat, enc);
    }
    k_mlp<<<NB, 64>>>(rel, kge, W1, b1, W2, b2, out);
}

// round 7
// speedup vs baseline: 1.7259x; 1.3021x over previous
#include <cuda_runtime.h>
#include <cuda_bf16.h>
#include <stdint.h>
#include <math.h>

#define NN 50000
#define NE 800000
#define ET (NN + NE)
#define NB 512
#define ND 256
#define NH 4
#define HC 64

// ---------------- static device scratch ----------------
__device__ float g_x[(size_t)NN * ND];
__device__ __nv_bfloat16 g_xhi[(size_t)NN * ND];
__device__ __nv_bfloat16 g_xlo[(size_t)NN * ND];
__device__ __nv_bfloat16 g_whi[3 * ND * ND];   // transposed [l][n][k]
__device__ __nv_bfloat16 g_wlo[3 * ND * ND];
__device__ float g_h[(size_t)NN * ND];
__device__ float g_asrc[NN * NH];
__device__ float g_adst[NN * NH];
__device__ float g_alpha[(size_t)NH * ET];
__device__ int   g_counts[NN];
__device__ int   g_off[NN];
__device__ int   g_cur[NN];
__device__ int   g_srcs[ET];
__device__ int   g_dsts[ET];
__device__ int   g_total;
__device__ float g_he[NB * ND];
__device__ float g_te[NB * ND];

// ---------------- fp32 -> bf16 hi/lo split ----------------
__device__ __forceinline__ void split_bf16(float v, __nv_bfloat16& hi, __nv_bfloat16& lo) {
    hi = __float2bfloat16(v);
    lo = __float2bfloat16(v - __bfloat162float(hi));
}

__global__ void k_split_x(const float* __restrict__ x) {
    int i = blockIdx.x * blockDim.x + threadIdx.x;
    int stride = gridDim.x * blockDim.x;
    for (; i < NN * ND; i += stride) {
        __nv_bfloat16 hi, lo;
        split_bf16(x[i], hi, lo);
        g_xhi[i] = hi;
        g_xlo[i] = lo;
    }
}

__global__ void k_split_w(const float* __restrict__ Ws) {
    int i = blockIdx.x * blockDim.x + threadIdx.x;
    if (i >= 3 * ND * ND) return;
    int l = i / (ND * ND);
    int r = i % (ND * ND);
    int n = r / ND;
    int k = r % ND;
    float v = Ws[l * ND * ND + k * ND + n];
    __nv_bfloat16 hi, lo;
    split_bf16(v, hi, lo);
    g_whi[i] = hi;
    g_wlo[i] = lo;
}

// ---------------- CSR construction (scan-free) ----------------
__global__ void k_init_counts() {
    int i = blockIdx.x * blockDim.x + threadIdx.x;
    if (i < NN) g_counts[i] = 1;   // self-loop pre-counted
    if (i == 0) g_total = 0;
}

__global__ void k_count(const int* __restrict__ ei) {
    int e = blockIdx.x * blockDim.x + threadIdx.x;
    if (e < NE) atomicAdd(&g_counts[ei[NE + e]], 1);
}

// warp-aggregated segment allocator
__global__ void k_assign() {
    int i = blockIdx.x * blockDim.x + threadIdx.x;
    int lane = threadIdx.x & 31;
    int v = (i < NN) ? g_counts[i] : 0;
    int inc = v;
#pragma unroll
    for (int o = 1; o < 32; o <<= 1) {
        int t = __shfl_up_sync(0xffffffffu, inc, o);
        if (lane >= o) inc += t;
    }
    int wtot = __shfl_sync(0xffffffffu, inc, 31);
    int base = 0;
    if (lane == 31) base = atomicAdd(&g_total, wtot);
    base = __shfl_sync(0xffffffffu, base, 31);
    if (i < NN) {
        int p = base + inc - v;
        g_off[i] = p;
        g_cur[i] = p;
    }
}

__global__ void k_scatter(const int* __restrict__ ei) {
    int e = blockIdx.x * blockDim.x + threadIdx.x;
    if (e >= NE) return;
    int s = ei[e], d = ei[NE + e];
    int p = atomicAdd(&g_cur[d], 1);
    g_srcs[p] = s;
    g_dsts[p] = d;
}

__global__ void k_selfloops() {
    int i = blockIdx.x * blockDim.x + threadIdx.x;
    if (i >= NN) return;
    int p = atomicAdd(&g_cur[i], 1);
    g_srcs[p] = i;
    g_dsts[p] = i;
}

// ---------------- bf16x3 tensor-core GEMM with cp.async double buffering ----------------
__device__ __forceinline__ void mma16816(float* c, const unsigned* a, const unsigned* b) {
    asm volatile(
        "mma.sync.aligned.m16n8k16.row.col.f32.bf16.bf16.f32 "
        "{%0,%1,%2,%3},{%4,%5,%6,%7},{%8,%9},{%0,%1,%2,%3};"
        : "+f"(c[0]), "+f"(c[1]), "+f"(c[2]), "+f"(c[3])
        : "r"(a[0]), "r"(a[1]), "r"(a[2]), "r"(a[3]), "r"(b[0]), "r"(b[1]));
}

#define LDP 40               // bf16 elems per smem row (80B pitch) -> conflict-free
#define ARR_B 10240          // bytes per array (128*40*2)
#define BUF_B 40960          // bytes per buffer (4 arrays)
#define GSMEM (2 * BUF_B)    // 80 KB

__device__ __forceinline__ void cp16(uint32_t dst, const void* src, bool pred) {
    asm volatile("cp.async.cg.shared.global [%0], [%1], 16, %2;"
                 :: "r"(dst), "l"(src), "r"(pred ? 16 : 0));
}

__global__ void __launch_bounds__(256, 2) k_gemm(const __nv_bfloat16* __restrict__ whi,
                                                 const __nv_bfloat16* __restrict__ wlo) {
    extern __shared__ __align__(16) unsigned char smem[];
    uint32_t smem_s = (uint32_t)__cvta_generic_to_shared(smem);
    int tid = threadIdx.x;
    int mBase = blockIdx.y * 128, nBase = blockIdx.x * 128;
    int w = tid >> 5, lane = tid & 31;
    int wm = w >> 2, wn = w & 3;
    int g = lane >> 2, thr = lane & 3;
    float c[4][4][4];
#pragma unroll
    for (int a = 0; a < 4; a++)
#pragma unroll
        for (int b = 0; b < 4; b++)
#pragma unroll
            for (int d = 0; d < 4; d++) c[a][b][d] = 0.f;

    // per-thread copy assignment: 2 chunks/array, chunk = 16B = 8 bf16
    int i0 = tid, i1 = tid + 256;
    int r0c = i0 >> 2, ch0 = (i0 & 3) * 8;
    int r1c = i1 >> 2, ch1 = (i1 & 3) * 8;
    bool p0 = (mBase + r0c) < NN, p1 = (mBase + r1c) < NN;
    size_t aof0 = (size_t)(mBase + r0c) * ND + ch0;
    size_t aof1 = (size_t)(mBase + r1c) * ND + ch1;
    size_t bof0 = (size_t)(nBase + r0c) * ND + ch0;
    size_t bof1 = (size_t)(nBase + r1c) * ND + ch1;
    uint32_t d00 = smem_s + r0c * 80 + ch0 * 2;
    uint32_t d01 = smem_s + r1c * 80 + ch1 * 2;

    auto issue = [&](int t, int buf) {
        int k0 = t * 32;
        uint32_t bb = (uint32_t)buf * BUF_B;
        cp16(d00 + bb,             g_xhi + aof0 + k0, p0);
        cp16(d01 + bb,             g_xhi + aof1 + k0, p1);
        cp16(d00 + bb + ARR_B,     g_xlo + aof0 + k0, p0);
        cp16(d01 + bb + ARR_B,     g_xlo + aof1 + k0, p1);
        cp16(d00 + bb + 2 * ARR_B, whi + bof0 + k0, true);
        cp16(d01 + bb + 2 * ARR_B, whi + bof1 + k0, true);
        cp16(d00 + bb + 3 * ARR_B, wlo + bof0 + k0, true);
        cp16(d01 + bb + 3 * ARR_B, wlo + bof1 + k0, true);
        asm volatile("cp.async.commit_group;");
    };

    issue(0, 0);
    for (int t = 0; t < 8; t++) {
        if (t < 7) {
            issue(t + 1, (t + 1) & 1);
            asm volatile("cp.async.wait_group 1;");
        } else {
            asm volatile("cp.async.wait_group 0;");
        }
        __syncthreads();

        const __nv_bfloat16* Ah = (const __nv_bfloat16*)(smem + (t & 1) * BUF_B);
        const __nv_bfloat16* Al = Ah + 5120;
        const __nv_bfloat16* Bh = Ah + 10240;
        const __nv_bfloat16* Bl = Ah + 15360;

#pragma unroll
        for (int kk = 0; kk < 32; kk += 16) {
            unsigned bhf[4][2], blf[4][2];
#pragma unroll
            for (int ni = 0; ni < 4; ni++) {
                int nr = wn * 32 + ni * 8 + g;
                bhf[ni][0] = *(const unsigned*)&Bh[nr * LDP + kk + thr * 2];
                bhf[ni][1] = *(const unsigned*)&Bh[nr * LDP + kk + thr * 2 + 8];
                blf[ni][0] = *(const unsigned*)&Bl[nr * LDP + kk + thr * 2];
                blf[ni][1] = *(const unsigned*)&Bl[nr * LDP + kk + thr * 2 + 8];
            }
#pragma unroll
            for (int mi = 0; mi < 4; mi++) {
                int r0 = wm * 64 + mi * 16 + g;
                unsigned ahf[4], alf[4];
                ahf[0] = *(const unsigned*)&Ah[r0 * LDP + kk + thr * 2];
                ahf[1] = *(const unsigned*)&Ah[(r0 + 8) * LDP + kk + thr * 2];
                ahf[2] = *(const unsigned*)&Ah[r0 * LDP + kk + thr * 2 + 8];
                ahf[3] = *(const unsigned*)&Ah[(r0 + 8) * LDP + kk + thr * 2 + 8];
                alf[0] = *(const unsigned*)&Al[r0 * LDP + kk + thr * 2];
                alf[1] = *(const unsigned*)&Al[(r0 + 8) * LDP + kk + thr * 2];
                alf[2] = *(const unsigned*)&Al[r0 * LDP + kk + thr * 2 + 8];
                alf[3] = *(const unsigned*)&Al[(r0 + 8) * LDP + kk + thr * 2 + 8];
#pragma unroll
                for (int ni = 0; ni < 4; ni++) {
                    mma16816(c[mi][ni], ahf, bhf[ni]);
                    mma16816(c[mi][ni], ahf, blf[ni]);
                    mma16816(c[mi][ni], alf, bhf[ni]);
                }
            }
        }
        __syncthreads();
    }

#pragma unroll
    for (int mi = 0; mi < 4; mi++) {
        int row0 = mBase + wm * 64 + mi * 16 + g;
#pragma unroll
        for (int ni = 0; ni < 4; ni++) {
            int col = nBase + wn * 32 + ni * 8 + thr * 2;
            if (row0 < NN)
                *(float2*)&g_h[(size_t)row0 * ND + col] = make_float2(c[mi][ni][0], c[mi][ni][1]);
            if (row0 + 8 < NN)
                *(float2*)&g_h[(size_t)(row0 + 8) * ND + col] = make_float2(c[mi][ni][2], c[mi][ni][3]);
        }
    }
}

// ---------------- per-node attention scores ----------------
__global__ void k_att(const float* __restrict__ a_s, const float* __restrict__ a_d) {
    int gw = (blockIdx.x * blockDim.x + threadIdx.x) >> 5;
    int lane = threadIdx.x & 31;
    if (gw >= NN) return;
    const float* row = g_h + (size_t)gw * ND;
    float ps[4] = {0.f, 0.f, 0.f, 0.f}, pd[4] = {0.f, 0.f, 0.f, 0.f};
#pragma unroll
    for (int i = 0; i < 8; i++) {
        int c = i * 32 + lane;
        float v = row[c];
        ps[i >> 1] += v * a_s[c];
        pd[i >> 1] += v * a_d[c];
    }
#pragma unroll
    for (int hh = 0; hh < 4; hh++) {
        float v = ps[hh], w = pd[hh];
#pragma unroll
        for (int o = 16; o; o >>= 1) {
            v += __shfl_xor_sync(0xffffffffu, v, o);
            w += __shfl_xor_sync(0xffffffffu, w, o);
        }
        if (lane == 0) {
            g_asrc[gw * 4 + hh] = v;
            g_adst[gw * 4 + hh] = w;
        }
    }
}

// ---------------- alpha = leaky(asrc[s] + adst[d]) ----------------
__global__ void k_alpha() {
    int e = blockIdx.x * blockDim.x + threadIdx.x;
    if (e >= ET) return;
    int s = g_srcs[e], d = g_dsts[e];
    float4 as = *(const float4*)&g_asrc[s * 4];
    float4 ad = *(const float4*)&g_adst[d * 4];
    float v;
    v = as.x + ad.x; g_alpha[0 * (size_t)ET + e] = v > 0.f ? v : 0.2f * v;
    v = as.y + ad.y; g_alpha[1 * (size_t)ET + e] = v > 0.f ? v : 0.2f * v;
    v = as.z + ad.z; g_alpha[2 * (size_t)ET + e] = v > 0.f ? v : 0.2f * v;
    v = as.w + ad.w; g_alpha[3 * (size_t)ET + e] = v > 0.f ? v : 0.2f * v;
}

// ---------------- aggregation: segment softmax + weighted sum + bias + ELU ----------------
__global__ void __launch_bounds__(256) k_agg(const float* __restrict__ bias, int last) {
    int warp = threadIdx.x >> 5;
    int lane = threadIdx.x & 31;
    int node = blockIdx.x * 2 + (warp >> 2);
    int head = warp & 3;
    if (node >= NN) return;
    int beg = g_off[node];
    int cnt_all = g_counts[node];
    int end = beg + cnt_all;
    const float* al = g_alpha + (size_t)head * ET;

    int c2 = head * HC + lane * 2;  // each lane owns 2 adjacent columns
    float accx = 0.f, accy = 0.f, denom = 0.f;

    if (cnt_all <= 32) {
        bool ok = lane < cnt_all;
        float a = ok ? al[beg + lane] : -1e30f;
        int s = ok ? g_srcs[beg + lane] : 0;
        float m = a;
#pragma unroll
        for (int o = 16; o; o >>= 1) m = fmaxf(m, __shfl_xor_sync(0xffffffffu, m, o));
        float ea = ok ? __expf(a - m) : 0.f;
        denom = ea;
        for (int j = 0; j < cnt_all; j++) {
            float eaj = __shfl_sync(0xffffffffu, ea, j);
            int sj = __shfl_sync(0xffffffffu, s, j);
            float2 hv = *(const float2*)(g_h + (size_t)sj * ND + c2);
            accx += eaj * hv.x;
            accy += eaj * hv.y;
        }
    } else {
        float m = -1e30f;
        for (int i = beg + lane; i < end; i += 32) m = fmaxf(m, al[i]);
#pragma unroll
        for (int o = 16; o; o >>= 1) m = fmaxf(m, __shfl_xor_sync(0xffffffffu, m, o));
        for (int base = beg; base < end; base += 32) {
            int i = base + lane;
            float ea = 0.f;
            int s = 0;
            if (i < end) {
                ea = __expf(al[i] - m);
                s = g_srcs[i];
            }
            denom += ea;
            int cnt = min(32, end - base);
            for (int j = 0; j < cnt; j++) {
                float eaj = __shfl_sync(0xffffffffu, ea, j);
                int sj = __shfl_sync(0xffffffffu, s, j);
                float2 hv = *(const float2*)(g_h + (size_t)sj * ND + c2);
                accx += eaj * hv.x;
                accy += eaj * hv.y;
            }
        }
    }
#pragma unroll
    for (int o = 16; o; o >>= 1) denom += __shfl_xor_sync(0xffffffffu, denom, o);

    float inv = 1.0f / denom;
    float v0 = accx * inv + bias[c2];
    float v1 = accy * inv + bias[c2 + 1];
    v0 = v0 > 0.f ? v0 : expm1f(v0);
    v1 = v1 > 0.f ? v1 : expm1f(v1);

    size_t o0 = (size_t)node * ND + c2;
    __nv_bfloat16 h0, l0, h1, l1;
    split_bf16(v0, h0, l0);
    split_bf16(v1, h1, l1);
    *(__nv_bfloat162*)(g_xhi + o0) = __nv_bfloat162(h0, h1);
    *(__nv_bfloat162*)(g_xlo + o0) = __nv_bfloat162(l0, l1);
    if (last) *(float2*)(g_x + o0) = make_float2(v0, v1);
}

// ---------------- pooling ----------------
__global__ void k_pool(const int* __restrict__ batch, int which) {
    __shared__ int sb, se;
    int b = blockIdx.x;
    if (threadIdx.x == 0) {
        int lo = 0, hi = NN;
        while (lo < hi) { int mid = (lo + hi) >> 1; if (batch[mid] < b) lo = mid + 1; else hi = mid; }
        sb = lo;
        lo = 0; hi = NN;
        while (lo < hi) { int mid = (lo + hi) >> 1; if (batch[mid] < b + 1) lo = mid + 1; else hi = mid; }
        se = lo;
    }
    __syncthreads();
    int c = threadIdx.x;
    float acc = 0.f;
    for (int i = sb; i < se; i++) acc += g_x[(size_t)i * ND + c];
    (which ? g_te : g_he)[b * ND + c] = acc;
}

// ---------------- final MLP ----------------
__global__ void k_mlp(const int* __restrict__ rel, const float* __restrict__ kge,
                      const float* __restrict__ W1, const float* __restrict__ b1,
                      const float* __restrict__ W2, const float* __restrict__ b2,
                      float* __restrict__ out) {
    int b = blockIdx.x;
    int j = threadIdx.x;
    __shared__ float zin[2 * ND + HC];
    for (int k = j; k < ND; k += 64) zin[k] = g_he[b * ND + k];
    for (int k = j; k < ND; k += 64) zin[ND + k] = g_te[b * ND + k];
    int r = rel[b];
    zin[2 * ND + j] = kge[r * HC + j];
    __syncthreads();
    float z = b1[j];
    for (int k = 0; k < 2 * ND + HC; k++) z += zin[k] * W1[k * 64 + j];
    z = fmaxf(z, 0.f);
    __shared__ float zs[64];
    zs[j] = z * W2[j];
    __syncthreads();
    if (j < 32) {
        float v = zs[j] + zs[j + 32];
#pragma unroll
        for (int o = 16; o; o >>= 1) v += __shfl_xor_sync(0xffffffffu, v, o);
        if (j == 0) out[b] = v + b2[0];
    }
}

// ---------------- launcher ----------------
extern "C" void kernel_launch(void* const* d_in, const int* in_sizes, int n_in,
                              void* d_out, int out_size) {
    const float* head_x    = (const float*)d_in[0];
    const int*   head_ei   = (const int*)d_in[1];
    const int*   head_b    = (const int*)d_in[2];
    const float* tail_x    = (const float*)d_in[3];
    const int*   tail_ei   = (const int*)d_in[4];
    const int*   tail_b    = (const int*)d_in[5];
    const int*   rel       = (const int*)d_in[6];
    const float* Ws        = (const float*)d_in[7];
    const float* att_src   = (const float*)d_in[8];
    const float* att_dst   = (const float*)d_in[9];
    const float* biases    = (const float*)d_in[10];
    const float* kge       = (const float*)d_in[11];
    const float* W1        = (const float*)d_in[12];
    const float* b1        = (const float*)d_in[13];
    const float* W2        = (const float*)d_in[14];
    const float* b2        = (const float*)d_in[15];
    float*       out       = (float*)d_out;

    cudaFuncSetAttribute(k_gemm, cudaFuncAttributeMaxDynamicSharedMemorySize, GSMEM);

    const int TB = 256;
    k_split_w<<<(3 * ND * ND + TB - 1) / TB, TB>>>(Ws);

    __nv_bfloat16 *whi0, *wlo0;
    cudaGetSymbolAddress((void**)&whi0, g_whi);
    cudaGetSymbolAddress((void**)&wlo0, g_wlo);

    for (int enc = 0; enc < 2; enc++) {
        const float* x0   = enc ? tail_x : head_x;
        const int*   ei   = enc ? tail_ei : head_ei;
        const int*   bat  = enc ? tail_b : head_b;

        k_init_counts<<<(NN + TB - 1) / TB, TB>>>();
        k_count<<<(NE + TB - 1) / TB, TB>>>(ei);
        k_assign<<<(NN + TB - 1) / TB, TB>>>();
        k_scatter<<<(NE + TB - 1) / TB, TB>>>(ei);
        k_selfloops<<<(NN + TB - 1) / TB, TB>>>();

        k_split_x<<<592, 256>>>(x0);

        for (int l = 0; l < 3; l++) {
            k_gemm<<<dim3(2, (NN + 127) / 128), 256, GSMEM>>>(whi0 + (size_t)l * ND * ND,
                                                              wlo0 + (size_t)l * ND * ND);
            k_att<<<(NN * 32 + TB - 1) / TB, TB>>>(att_src + l * ND, att_dst + l * ND);
            k_alpha<<<(ET + TB - 1) / TB, TB>>>();
            k_agg<<<NN / 2, 256>>>(biases + l * ND, l == 2);
        }
        k_pool<<<NB, ND>>>(bat, enc);
    }
    k_mlp<<<NB, 64>>>(rel, kge, W1, b1, W2, b2, out);
}

// round 8
// speedup vs baseline: 1.7666x; 1.0236x over previous
#include <cuda_runtime.h>
#include <cuda_bf16.h>
#include <stdint.h>
#include <math.h>

#define NN 50000
#define NE 800000
#define ET (NN + NE)
#define NB 512
#define ND 256
#define NH 4
#define HC 64

// ---------------- static device scratch ----------------
__device__ float g_x[(size_t)NN * ND];
__device__ __nv_bfloat16 g_xhi[(size_t)NN * ND];
__device__ __nv_bfloat16 g_xlo[(size_t)NN * ND];
__device__ __nv_bfloat16 g_whi[3 * ND * ND];   // transposed [l][n][k]
__device__ __nv_bfloat16 g_wlo[3 * ND * ND];
__device__ float g_h[(size_t)NN * ND];
__device__ float g_asrc[NN * NH];
__device__ float g_adst[NN * NH];
__device__ int   g_counts[NN];
__device__ int   g_off[NN];
__device__ int   g_cur[NN];
__device__ int   g_srcs[ET];
__device__ int   g_total;
__device__ float g_he[NB * ND];
__device__ float g_te[NB * ND];

// ---------------- fp32 -> bf16 hi/lo split ----------------
__device__ __forceinline__ void split_bf16(float v, __nv_bfloat16& hi, __nv_bfloat16& lo) {
    hi = __float2bfloat16(v);
    lo = __float2bfloat16(v - __bfloat162float(hi));
}

__global__ void k_split_x(const float* __restrict__ x) {
    int i = blockIdx.x * blockDim.x + threadIdx.x;
    int stride = gridDim.x * blockDim.x;
    for (; i < NN * ND; i += stride) {
        __nv_bfloat16 hi, lo;
        split_bf16(x[i], hi, lo);
        g_xhi[i] = hi;
        g_xlo[i] = lo;
    }
}

__global__ void k_split_w(const float* __restrict__ Ws) {
    int i = blockIdx.x * blockDim.x + threadIdx.x;
    if (i >= 3 * ND * ND) return;
    int l = i / (ND * ND);
    int r = i % (ND * ND);
    int n = r / ND;
    int k = r % ND;
    float v = Ws[l * ND * ND + k * ND + n];
    __nv_bfloat16 hi, lo;
    split_bf16(v, hi, lo);
    g_whi[i] = hi;
    g_wlo[i] = lo;
}

// ---------------- CSR construction (scan-free) ----------------
__global__ void k_init_counts() {
    int i = blockIdx.x * blockDim.x + threadIdx.x;
    if (i < NN) g_counts[i] = 1;   // self-loop pre-counted
    if (i == 0) g_total = 0;
}

__global__ void k_count(const int* __restrict__ ei) {
    int e = blockIdx.x * blockDim.x + threadIdx.x;
    if (e < NE) atomicAdd(&g_counts[ei[NE + e]], 1);
}

// warp-aggregated segment allocator
__global__ void k_assign() {
    int i = blockIdx.x * blockDim.x + threadIdx.x;
    int lane = threadIdx.x & 31;
    int v = (i < NN) ? g_counts[i] : 0;
    int inc = v;
#pragma unroll
    for (int o = 1; o < 32; o <<= 1) {
        int t = __shfl_up_sync(0xffffffffu, inc, o);
        if (lane >= o) inc += t;
    }
    int wtot = __shfl_sync(0xffffffffu, inc, 31);
    int base = 0;
    if (lane == 31) base = atomicAdd(&g_total, wtot);
    base = __shfl_sync(0xffffffffu, base, 31);
    if (i < NN) {
        int p = base + inc - v;
        g_off[i] = p;
        g_cur[i] = p;
    }
}

__global__ void k_scatter(const int* __restrict__ ei) {
    int e = blockIdx.x * blockDim.x + threadIdx.x;
    if (e >= NE) return;
    int s = ei[e], d = ei[NE + e];
    int p = atomicAdd(&g_cur[d], 1);
    g_srcs[p] = s;
}

__global__ void k_selfloops() {
    int i = blockIdx.x * blockDim.x + threadIdx.x;
    if (i >= NN) return;
    int p = atomicAdd(&g_cur[i], 1);
    g_srcs[p] = i;
}

// ---------------- bf16x3 tensor-core GEMM with cp.async double buffering ----------------
__device__ __forceinline__ void mma16816(float* c, const unsigned* a, const unsigned* b) {
    asm volatile(
        "mma.sync.aligned.m16n8k16.row.col.f32.bf16.bf16.f32 "
        "{%0,%1,%2,%3},{%4,%5,%6,%7},{%8,%9},{%0,%1,%2,%3};"
        : "+f"(c[0]), "+f"(c[1]), "+f"(c[2]), "+f"(c[3])
        : "r"(a[0]), "r"(a[1]), "r"(a[2]), "r"(a[3]), "r"(b[0]), "r"(b[1]));
}

#define LDP 40               // bf16 elems per smem row (80B pitch) -> conflict-free
#define ARR_B 10240          // bytes per array (128*40*2)
#define BUF_B 40960          // bytes per buffer (4 arrays)
#define GSMEM (2 * BUF_B)    // 80 KB

__device__ __forceinline__ void cp16(uint32_t dst, const void* src, bool pred) {
    asm volatile("cp.async.cg.shared.global [%0], [%1], 16, %2;"
                 :: "r"(dst), "l"(src), "r"(pred ? 16 : 0));
}

__global__ void __launch_bounds__(256, 2) k_gemm(const __nv_bfloat16* __restrict__ whi,
                                                 const __nv_bfloat16* __restrict__ wlo) {
    extern __shared__ __align__(16) unsigned char smem[];
    uint32_t smem_s = (uint32_t)__cvta_generic_to_shared(smem);
    int tid = threadIdx.x;
    int mBase = blockIdx.y * 128, nBase = blockIdx.x * 128;
    int w = tid >> 5, lane = tid & 31;
    int wm = w >> 2, wn = w & 3;
    int g = lane >> 2, thr = lane & 3;
    float c[4][4][4];
#pragma unroll
    for (int a = 0; a < 4; a++)
#pragma unroll
        for (int b = 0; b < 4; b++)
#pragma unroll
            for (int d = 0; d < 4; d++) c[a][b][d] = 0.f;

    int i0 = tid, i1 = tid + 256;
    int r0c = i0 >> 2, ch0 = (i0 & 3) * 8;
    int r1c = i1 >> 2, ch1 = (i1 & 3) * 8;
    bool p0 = (mBase + r0c) < NN, p1 = (mBase + r1c) < NN;
    size_t aof0 = (size_t)(mBase + r0c) * ND + ch0;
    size_t aof1 = (size_t)(mBase + r1c) * ND + ch1;
    size_t bof0 = (size_t)(nBase + r0c) * ND + ch0;
    size_t bof1 = (size_t)(nBase + r1c) * ND + ch1;
    uint32_t d00 = smem_s + r0c * 80 + ch0 * 2;
    uint32_t d01 = smem_s + r1c * 80 + ch1 * 2;

    auto issue = [&](int t, int buf) {
        int k0 = t * 32;
        uint32_t bb = (uint32_t)buf * BUF_B;
        cp16(d00 + bb,             g_xhi + aof0 + k0, p0);
        cp16(d01 + bb,             g_xhi + aof1 + k0, p1);
        cp16(d00 + bb + ARR_B,     g_xlo + aof0 + k0, p0);
        cp16(d01 + bb + ARR_B,     g_xlo + aof1 + k0, p1);
        cp16(d00 + bb + 2 * ARR_B, whi + bof0 + k0, true);
        cp16(d01 + bb + 2 * ARR_B, whi + bof1 + k0, true);
        cp16(d00 + bb + 3 * ARR_B, wlo + bof0 + k0, true);
        cp16(d01 + bb + 3 * ARR_B, wlo + bof1 + k0, true);
        asm volatile("cp.async.commit_group;");
    };

    issue(0, 0);
    for (int t = 0; t < 8; t++) {
        if (t < 7) {
            issue(t + 1, (t + 1) & 1);
            asm volatile("cp.async.wait_group 1;");
        } else {
            asm volatile("cp.async.wait_group 0;");
        }
        __syncthreads();

        const __nv_bfloat16* Ah = (const __nv_bfloat16*)(smem + (t & 1) * BUF_B);
        const __nv_bfloat16* Al = Ah + 5120;
        const __nv_bfloat16* Bh = Ah + 10240;
        const __nv_bfloat16* Bl = Ah + 15360;

#pragma unroll
        for (int kk = 0; kk < 32; kk += 16) {
            unsigned bhf[4][2], blf[4][2];
#pragma unroll
            for (int ni = 0; ni < 4; ni++) {
                int nr = wn * 32 + ni * 8 + g;
                bhf[ni][0] = *(const unsigned*)&Bh[nr * LDP + kk + thr * 2];
                bhf[ni][1] = *(const unsigned*)&Bh[nr * LDP + kk + thr * 2 + 8];
                blf[ni][0] = *(const unsigned*)&Bl[nr * LDP + kk + thr * 2];
                blf[ni][1] = *(const unsigned*)&Bl[nr * LDP + kk + thr * 2 + 8];
            }
#pragma unroll
            for (int mi = 0; mi < 4; mi++) {
                int r0 = wm * 64 + mi * 16 + g;
                unsigned ahf[4], alf[4];
                ahf[0] = *(const unsigned*)&Ah[r0 * LDP + kk + thr * 2];
                ahf[1] = *(const unsigned*)&Ah[(r0 + 8) * LDP + kk + thr * 2];
                ahf[2] = *(const unsigned*)&Ah[r0 * LDP + kk + thr * 2 + 8];
                ahf[3] = *(const unsigned*)&Ah[(r0 + 8) * LDP + kk + thr * 2 + 8];
                alf[0] = *(const unsigned*)&Al[r0 * LDP + kk + thr * 2];
                alf[1] = *(const unsigned*)&Al[(r0 + 8) * LDP + kk + thr * 2];
                alf[2] = *(const unsigned*)&Al[r0 * LDP + kk + thr * 2 + 8];
                alf[3] = *(const unsigned*)&Al[(r0 + 8) * LDP + kk + thr * 2 + 8];
#pragma unroll
                for (int ni = 0; ni < 4; ni++) {
                    mma16816(c[mi][ni], ahf, bhf[ni]);
                    mma16816(c[mi][ni], ahf, blf[ni]);
                    mma16816(c[mi][ni], alf, bhf[ni]);
                }
            }
        }
        __syncthreads();
    }

#pragma unroll
    for (int mi = 0; mi < 4; mi++) {
        int row0 = mBase + wm * 64 + mi * 16 + g;
#pragma unroll
        for (int ni = 0; ni < 4; ni++) {
            int col = nBase + wn * 32 + ni * 8 + thr * 2;
            if (row0 < NN)
                *(float2*)&g_h[(size_t)row0 * ND + col] = make_float2(c[mi][ni][0], c[mi][ni][1]);
            if (row0 + 8 < NN)
                *(float2*)&g_h[(size_t)(row0 + 8) * ND + col] = make_float2(c[mi][ni][2], c[mi][ni][3]);
        }
    }
}

// ---------------- per-node attention scores ----------------
__global__ void k_att(const float* __restrict__ a_s, const float* __restrict__ a_d) {
    int gw = (blockIdx.x * blockDim.x + threadIdx.x) >> 5;
    int lane = threadIdx.x & 31;
    if (gw >= NN) return;
    const float* row = g_h + (size_t)gw * ND;
    float ps[4] = {0.f, 0.f, 0.f, 0.f}, pd[4] = {0.f, 0.f, 0.f, 0.f};
#pragma unroll
    for (int i = 0; i < 8; i++) {
        int c = i * 32 + lane;
        float v = row[c];
        ps[i >> 1] += v * a_s[c];
        pd[i >> 1] += v * a_d[c];
    }
#pragma unroll
    for (int hh = 0; hh < 4; hh++) {
        float v = ps[hh], w = pd[hh];
#pragma unroll
        for (int o = 16; o; o >>= 1) {
            v += __shfl_xor_sync(0xffffffffu, v, o);
            w += __shfl_xor_sync(0xffffffffu, w, o);
        }
        if (lane == 0) {
            g_asrc[gw * 4 + hh] = v;
            g_adst[gw * 4 + hh] = w;
        }
    }
}

// ---------------- aggregation: fused logits + segment softmax + weighted sum + ELU ----------------
__global__ void __launch_bounds__(256) k_agg(const float* __restrict__ bias, int last) {
    int warp = threadIdx.x >> 5;
    int lane = threadIdx.x & 31;
    int node = blockIdx.x * 2 + (warp >> 2);
    int head = warp & 3;
    if (node >= NN) return;
    int beg = g_off[node];
    int cnt_all = g_counts[node];
    int end = beg + cnt_all;
    float adst_n = g_adst[node * 4 + head];

    int c2 = head * HC + lane * 2;  // each lane owns 2 adjacent columns
    float accx = 0.f, accy = 0.f, denom = 0.f;

    if (cnt_all <= 32) {
        // fast path: whole segment in registers, single pass
        bool ok = lane < cnt_all;
        int s = ok ? g_srcs[beg + lane] : 0;
        float a = -1e30f;
        if (ok) {
            a = g_asrc[s * 4 + head] + adst_n;
            a = a > 0.f ? a : 0.2f * a;
        }
        float m = a;
#pragma unroll
        for (int o = 16; o; o >>= 1) m = fmaxf(m, __shfl_xor_sync(0xffffffffu, m, o));
        float ea = ok ? __expf(a - m) : 0.f;
        denom = ea;
        for (int j = 0; j < cnt_all; j++) {
            float eaj = __shfl_sync(0xffffffffu, ea, j);
            int sj = __shfl_sync(0xffffffffu, s, j);
            float2 hv = *(const float2*)(g_h + (size_t)sj * ND + c2);
            accx += eaj * hv.x;
            accy += eaj * hv.y;
        }
    } else {
        // pass 1: segment max (recompute logits; asrc gather is L2-resident)
        float m = -1e30f;
        for (int i = beg + lane; i < end; i += 32) {
            int s = g_srcs[i];
            float a = g_asrc[s * 4 + head] + adst_n;
            a = a > 0.f ? a : 0.2f * a;
            m = fmaxf(m, a);
        }
#pragma unroll
        for (int o = 16; o; o >>= 1) m = fmaxf(m, __shfl_xor_sync(0xffffffffu, m, o));
        // pass 2: exp-sum + gather
        for (int base = beg; base < end; base += 32) {
            int i = base + lane;
            float ea = 0.f;
            int s = 0;
            if (i < end) {
                s = g_srcs[i];
                float a = g_asrc[s * 4 + head] + adst_n;
                a = a > 0.f ? a : 0.2f * a;
                ea = __expf(a - m);
            }
            denom += ea;
            int cnt = min(32, end - base);
            for (int j = 0; j < cnt; j++) {
                float eaj = __shfl_sync(0xffffffffu, ea, j);
                int sj = __shfl_sync(0xffffffffu, s, j);
                float2 hv = *(const float2*)(g_h + (size_t)sj * ND + c2);
                accx += eaj * hv.x;
                accy += eaj * hv.y;
            }
        }
    }
#pragma unroll
    for (int o = 16; o; o >>= 1) denom += __shfl_xor_sync(0xffffffffu, denom, o);

    float inv = 1.0f / denom;
    float v0 = accx * inv + bias[c2];
    float v1 = accy * inv + bias[c2 + 1];
    v0 = v0 > 0.f ? v0 : expm1f(v0);
    v1 = v1 > 0.f ? v1 : expm1f(v1);

    size_t o0 = (size_t)node * ND + c2;
    __nv_bfloat16 h0, l0, h1, l1;
    split_bf16(v0, h0, l0);
    split_bf16(v1, h1, l1);
    *(__nv_bfloat162*)(g_xhi + o0) = __nv_bfloat162(h0, h1);
    *(__nv_bfloat162*)(g_xlo + o0) = __nv_bfloat162(l0, l1);
    if (last) *(float2*)(g_x + o0) = make_float2(v0, v1);
}

// ---------------- pooling ----------------
__global__ void k_pool(const int* __restrict__ batch, int which) {
    __shared__ int sb, se;
    int b = blockIdx.x;
    if (threadIdx.x == 0) {
        int lo = 0, hi = NN;
        while (lo < hi) { int mid = (lo + hi) >> 1; if (batch[mid] < b) lo = mid + 1; else hi = mid; }
        sb = lo;
        lo = 0; hi = NN;
        while (lo < hi) { int mid = (lo + hi) >> 1; if (batch[mid] < b + 1) lo = mid + 1; else hi = mid; }
        se = lo;
    }
    __syncthreads();
    int c = threadIdx.x;
    float acc = 0.f;
    for (int i = sb; i < se; i++) acc += g_x[(size_t)i * ND + c];
    (which ? g_te : g_he)[b * ND + c] = acc;
}

// ---------------- final MLP ----------------
__global__ void k_mlp(const int* __restrict__ rel, const float* __restrict__ kge,
                      const float* __restrict__ W1, const float* __restrict__ b1,
                      const float* __restrict__ W2, const float* __restrict__ b2,
                      float* __restrict__ out) {
    int b = blockIdx.x;
    int j = threadIdx.x;
    __shared__ float zin[2 * ND + HC];
    for (int k = j; k < ND; k += 64) zin[k] = g_he[b * ND + k];
    for (int k = j; k < ND; k += 64) zin[ND + k] = g_te[b * ND + k];
    int r = rel[b];
    zin[2 * ND + j] = kge[r * HC + j];
    __syncthreads();
    float z = b1[j];
    for (int k = 0; k < 2 * ND + HC; k++) z += zin[k] * W1[k * 64 + j];
    z = fmaxf(z, 0.f);
    __shared__ float zs[64];
    zs[j] = z * W2[j];
    __syncthreads();
    if (j < 32) {
        float v = zs[j] + zs[j + 32];
#pragma unroll
        for (int o = 16; o; o >>= 1) v += __shfl_xor_sync(0xffffffffu, v, o);
        if (j == 0) out[b] = v + b2[0];
    }
}

// ---------------- launcher ----------------
extern "C" void kernel_launch(void* const* d_in, const int* in_sizes, int n_in,
                              void* d_out, int out_size) {
    const float* head_x    = (const float*)d_in[0];
    const int*   head_ei   = (const int*)d_in[1];
    const int*   head_b    = (const int*)d_in[2];
    const float* tail_x    = (const float*)d_in[3];
    const int*   tail_ei   = (const int*)d_in[4];
    const int*   tail_b    = (const int*)d_in[5];
    const int*   rel       = (const int*)d_in[6];
    const float* Ws        = (const float*)d_in[7];
    const float* att_src   = (const float*)d_in[8];
    const float* att_dst   = (const float*)d_in[9];
    const float* biases    = (const float*)d_in[10];
    const float* kge       = (const float*)d_in[11];
    const float* W1        = (const float*)d_in[12];
    const float* b1        = (const float*)d_in[13];
    const float* W2        = (const float*)d_in[14];
    const float* b2        = (const float*)d_in[15];
    float*       out       = (float*)d_out;

    cudaFuncSetAttribute(k_gemm, cudaFuncAttributeMaxDynamicSharedMemorySize, GSMEM);

    const int TB = 256;
    k_split_w<<<(3 * ND * ND + TB - 1) / TB, TB>>>(Ws);

    __nv_bfloat16 *whi0, *wlo0;
    cudaGetSymbolAddress((void**)&whi0, g_whi);
    cudaGetSymbolAddress((void**)&wlo0, g_wlo);

    for (int enc = 0; enc < 2; enc++) {
        const float* x0   = enc ? tail_x : head_x;
        const int*   ei   = enc ? tail_ei : head_ei;
        const int*   bat  = enc ? tail_b : head_b;

        k_init_counts<<<(NN + TB - 1) / TB, TB>>>();
        k_count<<<(NE + TB - 1) / TB, TB>>>(ei);
        k_assign<<<(NN + TB - 1) / TB, TB>>>();
        k_scatter<<<(NE + TB - 1) / TB, TB>>>(ei);
        k_selfloops<<<(NN + TB - 1) / TB, TB>>>();

        k_split_x<<<592, 256>>>(x0);

        for (int l = 0; l < 3; l++) {
            k_gemm<<<dim3(2, (NN + 127) / 128), 256, GSMEM>>>(whi0 + (size_t)l * ND * ND,
                                                              wlo0 + (size_t)l * ND * ND);
            k_att<<<(NN * 32 + TB - 1) / TB, TB>>>(att_src + l * ND, att_dst + l * ND);
            k_agg<<<NN / 2, 256>>>(biases + l * ND, l == 2);
        }
        k_pool<<<NB, ND>>>(bat, enc);
    }
    k_mlp<<<NB, 64>>>(rel, kge, W1, b1, W2, b2, out);
}

// round 9
// speedup vs baseline: 1.9427x; 1.0996x over previous
#include <cuda_runtime.h>
#include <cuda_bf16.h>
#include <stdint.h>
#include <math.h>

#define NN 50000
#define NN2 (2 * NN)          // both encoders merged: tail nodes at +NN
#define NE 800000
#define ET2 (2 * (NN + NE))   // merged edge arena (incl. self loops)
#define NB 512
#define ND 256
#define NH 4
#define HC 64

// ---------------- static device scratch ----------------
__device__ float g_x[(size_t)NN2 * ND];
__device__ __nv_bfloat16 g_xhi[(size_t)NN2 * ND];
__device__ __nv_bfloat16 g_xlo[(size_t)NN2 * ND];
__device__ __nv_bfloat16 g_whi[3 * ND * ND];   // transposed [l][n][k]
__device__ __nv_bfloat16 g_wlo[3 * ND * ND];
__device__ float g_h[(size_t)NN2 * ND];
__device__ float g_asrc[NN2 * NH];
__device__ float g_adst[NN2 * NH];
__device__ int   g_counts[NN2];
__device__ int   g_off[NN2];
__device__ int   g_cur[NN2];
__device__ int   g_srcs[ET2];
__device__ int   g_total;
__device__ float g_he[NB * ND];
__device__ float g_te[NB * ND];

// ---------------- fp32 -> bf16 hi/lo split ----------------
__device__ __forceinline__ void split_bf16(float v, __nv_bfloat16& hi, __nv_bfloat16& lo) {
    hi = __float2bfloat16(v);
    lo = __float2bfloat16(v - __bfloat162float(hi));
}

// both encoder inputs in one pass
__global__ void k_split_x(const float* __restrict__ xh, const float* __restrict__ xt) {
    int i = blockIdx.x * blockDim.x + threadIdx.x;
    int stride = gridDim.x * blockDim.x;
    for (; i < NN2 * ND; i += stride) {
        float v = (i < NN * ND) ? xh[i] : xt[i - NN * ND];
        __nv_bfloat16 hi, lo;
        split_bf16(v, hi, lo);
        g_xhi[i] = hi;
        g_xlo[i] = lo;
    }
}

__global__ void k_split_w(const float* __restrict__ Ws) {
    int i = blockIdx.x * blockDim.x + threadIdx.x;
    if (i >= 3 * ND * ND) return;
    int l = i / (ND * ND);
    int r = i % (ND * ND);
    int n = r / ND;
    int k = r % ND;
    float v = Ws[l * ND * ND + k * ND + n];
    __nv_bfloat16 hi, lo;
    split_bf16(v, hi, lo);
    g_whi[i] = hi;
    g_wlo[i] = lo;
}

// ---------------- merged CSR construction ----------------
__global__ void k_init_counts() {
    int i = blockIdx.x * blockDim.x + threadIdx.x;
    if (i < NN2) g_counts[i] = 1;   // self-loop pre-counted
    if (i == 0) g_total = 0;
}

__global__ void k_count(const int* __restrict__ eh, const int* __restrict__ et) {
    int e = blockIdx.x * blockDim.x + threadIdx.x;
    if (e >= 2 * NE) return;
    int d = (e < NE) ? eh[NE + e] : (et[NE + (e - NE)] + NN);
    atomicAdd(&g_counts[d], 1);
}

// warp-aggregated segment allocator
__global__ void k_assign() {
    int i = blockIdx.x * blockDim.x + threadIdx.x;
    int lane = threadIdx.x & 31;
    int v = (i < NN2) ? g_counts[i] : 0;
    int inc = v;
#pragma unroll
    for (int o = 1; o < 32; o <<= 1) {
        int t = __shfl_up_sync(0xffffffffu, inc, o);
        if (lane >= o) inc += t;
    }
    int wtot = __shfl_sync(0xffffffffu, inc, 31);
    int base = 0;
    if (lane == 31) base = atomicAdd(&g_total, wtot);
    base = __shfl_sync(0xffffffffu, base, 31);
    if (i < NN2) {
        int p = base + inc - v;
        g_off[i] = p;
        g_cur[i] = p;
    }
}

__global__ void k_scatter(const int* __restrict__ eh, const int* __restrict__ et) {
    int e = blockIdx.x * blockDim.x + threadIdx.x;
    if (e >= 2 * NE) return;
    int s, d;
    if (e < NE) {
        s = eh[e];
        d = eh[NE + e];
    } else {
        s = et[e - NE] + NN;
        d = et[NE + (e - NE)] + NN;
    }
    int p = atomicAdd(&g_cur[d], 1);
    g_srcs[p] = s;
}

__global__ void k_selfloops() {
    int i = blockIdx.x * blockDim.x + threadIdx.x;
    if (i >= NN2) return;
    int p = atomicAdd(&g_cur[i], 1);
    g_srcs[p] = i;
}

// ---------------- bf16x3 tensor-core GEMM + fused att-score epilogue ----------------
__device__ __forceinline__ void mma16816(float* c, const unsigned* a, const unsigned* b) {
    asm volatile(
        "mma.sync.aligned.m16n8k16.row.col.f32.bf16.bf16.f32 "
        "{%0,%1,%2,%3},{%4,%5,%6,%7},{%8,%9},{%0,%1,%2,%3};"
        : "+f"(c[0]), "+f"(c[1]), "+f"(c[2]), "+f"(c[3])
        : "r"(a[0]), "r"(a[1]), "r"(a[2]), "r"(a[3]), "r"(b[0]), "r"(b[1]));
}

#define LDP 40               // bf16 elems per smem row (80B pitch) -> conflict-free
#define ARR_B 10240          // bytes per array (128*40*2)
#define BUF_B 40960          // bytes per buffer (4 arrays)
#define GSMEM (2 * BUF_B)    // 80 KB

__device__ __forceinline__ void cp16(uint32_t dst, const void* src, bool pred) {
    asm volatile("cp.async.cg.shared.global [%0], [%1], 16, %2;"
                 :: "r"(dst), "l"(src), "r"(pred ? 16 : 0));
}

__global__ void __launch_bounds__(256, 2) k_gemm(const __nv_bfloat16* __restrict__ whi,
                                                 const __nv_bfloat16* __restrict__ wlo,
                                                 const float* __restrict__ a_s,
                                                 const float* __restrict__ a_d) {
    extern __shared__ __align__(16) unsigned char smem[];
    uint32_t smem_s = (uint32_t)__cvta_generic_to_shared(smem);
    int tid = threadIdx.x;
    int bx = blockIdx.x;
    int mBase = blockIdx.y * 128, nBase = bx * 128;
    int w = tid >> 5, lane = tid & 31;
    int wm = w >> 2, wn = w & 3;
    int g = lane >> 2, thr = lane & 3;
    float c[4][4][4];
#pragma unroll
    for (int a = 0; a < 4; a++)
#pragma unroll
        for (int b = 0; b < 4; b++)
#pragma unroll
            for (int d = 0; d < 4; d++) c[a][b][d] = 0.f;

    int i0 = tid, i1 = tid + 256;
    int r0c = i0 >> 2, ch0 = (i0 & 3) * 8;
    int r1c = i1 >> 2, ch1 = (i1 & 3) * 8;
    bool p0 = (mBase + r0c) < NN2, p1 = (mBase + r1c) < NN2;
    size_t aof0 = (size_t)(mBase + r0c) * ND + ch0;
    size_t aof1 = (size_t)(mBase + r1c) * ND + ch1;
    size_t bof0 = (size_t)(nBase + r0c) * ND + ch0;
    size_t bof1 = (size_t)(nBase + r1c) * ND + ch1;
    uint32_t d00 = smem_s + r0c * 80 + ch0 * 2;
    uint32_t d01 = smem_s + r1c * 80 + ch1 * 2;

    auto issue = [&](int t, int buf) {
        int k0 = t * 32;
        uint32_t bb = (uint32_t)buf * BUF_B;
        cp16(d00 + bb,             g_xhi + aof0 + k0, p0);
        cp16(d01 + bb,             g_xhi + aof1 + k0, p1);
        cp16(d00 + bb + ARR_B,     g_xlo + aof0 + k0, p0);
        cp16(d01 + bb + ARR_B,     g_xlo + aof1 + k0, p1);
        cp16(d00 + bb + 2 * ARR_B, whi + bof0 + k0, true);
        cp16(d01 + bb + 2 * ARR_B, whi + bof1 + k0, true);
        cp16(d00 + bb + 3 * ARR_B, wlo + bof0 + k0, true);
        cp16(d01 + bb + 3 * ARR_B, wlo + bof1 + k0, true);
        asm volatile("cp.async.commit_group;");
    };

    issue(0, 0);
    for (int t = 0; t < 8; t++) {
        if (t < 7) {
            issue(t + 1, (t + 1) & 1);
            asm volatile("cp.async.wait_group 1;");
        } else {
            asm volatile("cp.async.wait_group 0;");
        }
        __syncthreads();

        const __nv_bfloat16* Ah = (const __nv_bfloat16*)(smem + (t & 1) * BUF_B);
        const __nv_bfloat16* Al = Ah + 5120;
        const __nv_bfloat16* Bh = Ah + 10240;
        const __nv_bfloat16* Bl = Ah + 15360;

#pragma unroll
        for (int kk = 0; kk < 32; kk += 16) {
            unsigned bhf[4][2], blf[4][2];
#pragma unroll
            for (int ni = 0; ni < 4; ni++) {
                int nr = wn * 32 + ni * 8 + g;
                bhf[ni][0] = *(const unsigned*)&Bh[nr * LDP + kk + thr * 2];
                bhf[ni][1] = *(const unsigned*)&Bh[nr * LDP + kk + thr * 2 + 8];
                blf[ni][0] = *(const unsigned*)&Bl[nr * LDP + kk + thr * 2];
                blf[ni][1] = *(const unsigned*)&Bl[nr * LDP + kk + thr * 2 + 8];
            }
#pragma unroll
            for (int mi = 0; mi < 4; mi++) {
                int r0 = wm * 64 + mi * 16 + g;
                unsigned ahf[4], alf[4];
                ahf[0] = *(const unsigned*)&Ah[r0 * LDP + kk + thr * 2];
                ahf[1] = *(const unsigned*)&Ah[(r0 + 8) * LDP + kk + thr * 2];
                ahf[2] = *(const unsigned*)&Ah[r0 * LDP + kk + thr * 2 + 8];
                ahf[3] = *(const unsigned*)&Ah[(r0 + 8) * LDP + kk + thr * 2 + 8];
                alf[0] = *(const unsigned*)&Al[r0 * LDP + kk + thr * 2];
                alf[1] = *(const unsigned*)&Al[(r0 + 8) * LDP + kk + thr * 2];
                alf[2] = *(const unsigned*)&Al[r0 * LDP + kk + thr * 2 + 8];
                alf[3] = *(const unsigned*)&Al[(r0 + 8) * LDP + kk + thr * 2 + 8];
#pragma unroll
                for (int ni = 0; ni < 4; ni++) {
                    mma16816(c[mi][ni], ahf, bhf[ni]);
                    mma16816(c[mi][ni], ahf, blf[ni]);
                    mma16816(c[mi][ni], alf, bhf[ni]);
                }
            }
        }
        __syncthreads();
    }

    // ---- store h ----
#pragma unroll
    for (int mi = 0; mi < 4; mi++) {
        int row0 = mBase + wm * 64 + mi * 16 + g;
#pragma unroll
        for (int ni = 0; ni < 4; ni++) {
            int col = nBase + wn * 32 + ni * 8 + thr * 2;
            if (row0 < NN2)
                *(float2*)&g_h[(size_t)row0 * ND + col] = make_float2(c[mi][ni][0], c[mi][ni][1]);
            if (row0 + 8 < NN2)
                *(float2*)&g_h[(size_t)(row0 + 8) * ND + col] = make_float2(c[mi][ni][2], c[mi][ni][3]);
        }
    }

    // ---- fused attention-score epilogue ----
    // block bx covers global cols [bx*128, bx*128+128) == heads {2bx, 2bx+1}
    float2 asv[4], adv[4];
#pragma unroll
    for (int ni = 0; ni < 4; ni++) {
        int col = nBase + wn * 32 + ni * 8 + thr * 2;
        asv[ni] = *(const float2*)&a_s[col];
        adv[ni] = *(const float2*)&a_d[col];
    }
    float ps[4][2], pd[4][2];
#pragma unroll
    for (int mi = 0; mi < 4; mi++) {
        ps[mi][0] = ps[mi][1] = pd[mi][0] = pd[mi][1] = 0.f;
#pragma unroll
        for (int ni = 0; ni < 4; ni++) {
            ps[mi][0] += c[mi][ni][0] * asv[ni].x + c[mi][ni][1] * asv[ni].y;
            ps[mi][1] += c[mi][ni][2] * asv[ni].x + c[mi][ni][3] * asv[ni].y;
            pd[mi][0] += c[mi][ni][0] * adv[ni].x + c[mi][ni][1] * adv[ni].y;
            pd[mi][1] += c[mi][ni][2] * adv[ni].x + c[mi][ni][3] * adv[ni].y;
        }
    }
    // reduce over the 4-lane col group (thr)
#pragma unroll
    for (int off = 1; off < 4; off <<= 1) {
#pragma unroll
        for (int mi = 0; mi < 4; mi++) {
#pragma unroll
            for (int j = 0; j < 2; j++) {
                ps[mi][j] += __shfl_xor_sync(0xffffffffu, ps[mi][j], off);
                pd[mi][j] += __shfl_xor_sync(0xffffffffu, pd[mi][j], off);
            }
        }
    }
    float2* arr = (float2*)smem;   // [128 rows][4 wn] -> 4 KB
    if (thr == 0) {
#pragma unroll
        for (int mi = 0; mi < 4; mi++) {
#pragma unroll
            for (int j = 0; j < 2; j++) {
                int row = wm * 64 + mi * 16 + g + j * 8;
                arr[row * 4 + wn] = make_float2(ps[mi][j], pd[mi][j]);
            }
        }
    }
    __syncthreads();
    if (tid < 128) {
        int rg = mBase + tid;
        if (rg < NN2) {
            float2 q0 = arr[tid * 4 + 0], q1 = arr[tid * 4 + 1];
            float2 q2 = arr[tid * 4 + 2], q3 = arr[tid * 4 + 3];
            int hb = bx * 2;
            g_asrc[rg * 4 + hb]     = q0.x + q1.x;
            g_asrc[rg * 4 + hb + 1] = q2.x + q3.x;
            g_adst[rg * 4 + hb]     = q0.y + q1.y;
            g_adst[rg * 4 + hb + 1] = q2.y + q3.y;
        }
    }
}

// ---------------- aggregation: fused logits + segment softmax + weighted sum + ELU ----------------
__global__ void __launch_bounds__(256) k_agg(const float* __restrict__ bias, int last) {
    int warp = threadIdx.x >> 5;
    int lane = threadIdx.x & 31;
    int node = blockIdx.x * 2 + (warp >> 2);
    int head = warp & 3;
    if (node >= NN2) return;
    int beg = g_off[node];
    int cnt_all = g_counts[node];
    int end = beg + cnt_all;
    float adst_n = g_adst[node * 4 + head];

    int c2 = head * HC + lane * 2;
    float accx = 0.f, accy = 0.f, denom = 0.f;

    if (cnt_all <= 32) {
        bool ok = lane < cnt_all;
        int s = ok ? g_srcs[beg + lane] : 0;
        float a = -1e30f;
        if (ok) {
            a = g_asrc[s * 4 + head] + adst_n;
            a = a > 0.f ? a : 0.2f * a;
        }
        float m = a;
#pragma unroll
        for (int o = 16; o; o >>= 1) m = fmaxf(m, __shfl_xor_sync(0xffffffffu, m, o));
        float ea = ok ? __expf(a - m) : 0.f;
        denom = ea;
        for (int j = 0; j < cnt_all; j++) {
            float eaj = __shfl_sync(0xffffffffu, ea, j);
            int sj = __shfl_sync(0xffffffffu, s, j);
            float2 hv = *(const float2*)(g_h + (size_t)sj * ND + c2);
            accx += eaj * hv.x;
            accy += eaj * hv.y;
        }
    } else {
        float m = -1e30f;
        for (int i = beg + lane; i < end; i += 32) {
            int s = g_srcs[i];
            float a = g_asrc[s * 4 + head] + adst_n;
            a = a > 0.f ? a : 0.2f * a;
            m = fmaxf(m, a);
        }
#pragma unroll
        for (int o = 16; o; o >>= 1) m = fmaxf(m, __shfl_xor_sync(0xffffffffu, m, o));
        for (int base = beg; base < end; base += 32) {
            int i = base + lane;
            float ea = 0.f;
            int s = 0;
            if (i < end) {
                s = g_srcs[i];
                float a = g_asrc[s * 4 + head] + adst_n;
                a = a > 0.f ? a : 0.2f * a;
                ea = __expf(a - m);
            }
            denom += ea;
            int cnt = min(32, end - base);
            for (int j = 0; j < cnt; j++) {
                float eaj = __shfl_sync(0xffffffffu, ea, j);
                int sj = __shfl_sync(0xffffffffu, s, j);
                float2 hv = *(const float2*)(g_h + (size_t)sj * ND + c2);
                accx += eaj * hv.x;
                accy += eaj * hv.y;
            }
        }
    }
#pragma unroll
    for (int o = 16; o; o >>= 1) denom += __shfl_xor_sync(0xffffffffu, denom, o);

    float inv = 1.0f / denom;
    float v0 = accx * inv + bias[c2];
    float v1 = accy * inv + bias[c2 + 1];
    v0 = v0 > 0.f ? v0 : expm1f(v0);
    v1 = v1 > 0.f ? v1 : expm1f(v1);

    size_t o0 = (size_t)node * ND + c2;
    __nv_bfloat16 h0, l0, h1, l1;
    split_bf16(v0, h0, l0);
    split_bf16(v1, h1, l1);
    *(__nv_bfloat162*)(g_xhi + o0) = __nv_bfloat162(h0, h1);
    *(__nv_bfloat162*)(g_xlo + o0) = __nv_bfloat162(l0, l1);
    if (last) *(float2*)(g_x + o0) = make_float2(v0, v1);
}

// ---------------- pooling (both encoders, 1024 blocks) ----------------
__global__ void k_pool(const int* __restrict__ hb, const int* __restrict__ tb) {
    __shared__ int sb, se;
    int b = blockIdx.x;
    int which = b >= NB;
    int bb = which ? b - NB : b;
    const int* batch = which ? tb : hb;
    if (threadIdx.x == 0) {
        int lo = 0, hi = NN;
        while (lo < hi) { int mid = (lo + hi) >> 1; if (batch[mid] < bb) lo = mid + 1; else hi = mid; }
        sb = lo;
        lo = 0; hi = NN;
        while (lo < hi) { int mid = (lo + hi) >> 1; if (batch[mid] < bb + 1) lo = mid + 1; else hi = mid; }
        se = lo;
    }
    __syncthreads();
    int c = threadIdx.x;
    int base = which ? NN : 0;
    float acc = 0.f;
    for (int i = sb; i < se; i++) acc += g_x[(size_t)(base + i) * ND + c];
    (which ? g_te : g_he)[bb * ND + c] = acc;
}

// ---------------- final MLP ----------------
__global__ void k_mlp(const int* __restrict__ rel, const float* __restrict__ kge,
                      const float* __restrict__ W1, const float* __restrict__ b1,
                      const float* __restrict__ W2, const float* __restrict__ b2,
                      float* __restrict__ out) {
    int b = blockIdx.x;
    int j = threadIdx.x;
    __shared__ float zin[2 * ND + HC];
    for (int k = j; k < ND; k += 64) zin[k] = g_he[b * ND + k];
    for (int k = j; k < ND; k += 64) zin[ND + k] = g_te[b * ND + k];
    int r = rel[b];
    zin[2 * ND + j] = kge[r * HC + j];
    __syncthreads();
    float z = b1[j];
    for (int k = 0; k < 2 * ND + HC; k++) z += zin[k] * W1[k * 64 + j];
    z = fmaxf(z, 0.f);
    __shared__ float zs[64];
    zs[j] = z * W2[j];
    __syncthreads();
    if (j < 32) {
        float v = zs[j] + zs[j + 32];
#pragma unroll
        for (int o = 16; o; o >>= 1) v += __shfl_xor_sync(0xffffffffu, v, o);
        if (j == 0) out[b] = v + b2[0];
    }
}

// ---------------- launcher ----------------
extern "C" void kernel_launch(void* const* d_in, const int* in_sizes, int n_in,
                              void* d_out, int out_size) {
    const float* head_x    = (const float*)d_in[0];
    const int*   head_ei   = (const int*)d_in[1];
    const int*   head_b    = (const int*)d_in[2];
    const float* tail_x    = (const float*)d_in[3];
    const int*   tail_ei   = (const int*)d_in[4];
    const int*   tail_b    = (const int*)d_in[5];
    const int*   rel       = (const int*)d_in[6];
    const float* Ws        = (const float*)d_in[7];
    const float* att_src   = (const float*)d_in[8];
    const float* att_dst   = (const float*)d_in[9];
    const float* biases    = (const float*)d_in[10];
    const float* kge       = (const float*)d_in[11];
    const float* W1        = (const float*)d_in[12];
    const float* b1        = (const float*)d_in[13];
    const float* W2        = (const float*)d_in[14];
    const float* b2        = (const float*)d_in[15];
    float*       out       = (float*)d_out;

    cudaFuncSetAttribute(k_gemm, cudaFuncAttributeMaxDynamicSharedMemorySize, GSMEM);

    const int TB = 256;
    __nv_bfloat16 *whi0, *wlo0;
    cudaGetSymbolAddress((void**)&whi0, g_whi);
    cudaGetSymbolAddress((void**)&wlo0, g_wlo);

    k_split_w<<<(3 * ND * ND + TB - 1) / TB, TB>>>(Ws);
    k_init_counts<<<(NN2 + TB - 1) / TB, TB>>>();
    k_count<<<(2 * NE + TB - 1) / TB, TB>>>(head_ei, tail_ei);
    k_assign<<<(NN2 + TB - 1) / TB, TB>>>();
    k_scatter<<<(2 * NE + TB - 1) / TB, TB>>>(head_ei, tail_ei);
    k_selfloops<<<(NN2 + TB - 1) / TB, TB>>>();
    k_split_x<<<1184, 256>>>(head_x, tail_x);

    for (int l = 0; l < 3; l++) {
        k_gemm<<<dim3(2, (NN2 + 127) / 128), 256, GSMEM>>>(
            whi0 + (size_t)l * ND * ND, wlo0 + (size_t)l * ND * ND,
            att_src + l * ND, att_dst + l * ND);
        k_agg<<<NN2 / 2, 256>>>(biases + l * ND, l == 2);
    }
    k_pool<<<2 * NB, ND>>>(head_b, tail_b);
    k_mlp<<<NB, 64>>>(rel, kge, W1, b1, W2, b2, out);
}

// round 10
// speedup vs baseline: 2.0009x; 1.0299x over previous
#include <cuda_runtime.h>
#include <cuda_bf16.h>
#include <cuda_fp16.h>
#include <stdint.h>
#include <math.h>

#define NN 50000
#define NN2 (2 * NN)          // both encoders merged: tail nodes at +NN
#define NE 800000
#define ET2 (2 * (NN + NE))   // merged edge arena (incl. self loops)
#define NB 512
#define ND 256
#define NH 4
#define HC 64

// ---------------- static device scratch ----------------
__device__ float g_x[(size_t)NN2 * ND];
__device__ __nv_bfloat16 g_xhi[(size_t)NN2 * ND];
__device__ __nv_bfloat16 g_xlo[(size_t)NN2 * ND];
__device__ __nv_bfloat16 g_whi[3 * ND * ND];   // transposed [l][n][k]
__device__ __nv_bfloat16 g_wlo[3 * ND * ND];
__device__ __half g_hf[(size_t)NN2 * ND];      // h in fp16 (gather plane)
__device__ float g_asrc[NN2 * NH];
__device__ float g_adst[NN2 * NH];
__device__ int   g_counts[NN2];
__device__ int   g_off[NN2];
__device__ int   g_cur[NN2];
__device__ int   g_srcs[ET2];
__device__ int   g_total;
__device__ float g_he[NB * ND];
__device__ float g_te[NB * ND];

// ---------------- fp32 -> bf16 hi/lo split ----------------
__device__ __forceinline__ void split_bf16(float v, __nv_bfloat16& hi, __nv_bfloat16& lo) {
    hi = __float2bfloat16(v);
    lo = __float2bfloat16(v - __bfloat162float(hi));
}

__global__ void k_split_x(const float* __restrict__ xh, const float* __restrict__ xt) {
    int i = blockIdx.x * blockDim.x + threadIdx.x;
    int stride = gridDim.x * blockDim.x;
    for (; i < NN2 * ND; i += stride) {
        float v = (i < NN * ND) ? xh[i] : xt[i - NN * ND];
        __nv_bfloat16 hi, lo;
        split_bf16(v, hi, lo);
        g_xhi[i] = hi;
        g_xlo[i] = lo;
    }
}

__global__ void k_split_w(const float* __restrict__ Ws) {
    int i = blockIdx.x * blockDim.x + threadIdx.x;
    if (i >= 3 * ND * ND) return;
    int l = i / (ND * ND);
    int r = i % (ND * ND);
    int n = r / ND;
    int k = r % ND;
    float v = Ws[l * ND * ND + k * ND + n];
    __nv_bfloat16 hi, lo;
    split_bf16(v, hi, lo);
    g_whi[i] = hi;
    g_wlo[i] = lo;
}

// ---------------- merged CSR construction ----------------
__global__ void k_init_counts() {
    int i = blockIdx.x * blockDim.x + threadIdx.x;
    if (i < NN2) g_counts[i] = 1;   // self-loop pre-counted
    if (i == 0) g_total = 0;
}

__global__ void k_count(const int* __restrict__ eh, const int* __restrict__ et) {
    int e = blockIdx.x * blockDim.x + threadIdx.x;
    if (e >= 2 * NE) return;
    int d = (e < NE) ? eh[NE + e] : (et[NE + (e - NE)] + NN);
    atomicAdd(&g_counts[d], 1);
}

__global__ void k_assign() {
    int i = blockIdx.x * blockDim.x + threadIdx.x;
    int lane = threadIdx.x & 31;
    int v = (i < NN2) ? g_counts[i] : 0;
    int inc = v;
#pragma unroll
    for (int o = 1; o < 32; o <<= 1) {
        int t = __shfl_up_sync(0xffffffffu, inc, o);
        if (lane >= o) inc += t;
    }
    int wtot = __shfl_sync(0xffffffffu, inc, 31);
    int base = 0;
    if (lane == 31) base = atomicAdd(&g_total, wtot);
    base = __shfl_sync(0xffffffffu, base, 31);
    if (i < NN2) {
        int p = base + inc - v;
        g_off[i] = p;
        g_cur[i] = p;
    }
}

__global__ void k_scatter(const int* __restrict__ eh, const int* __restrict__ et) {
    int e = blockIdx.x * blockDim.x + threadIdx.x;
    if (e >= 2 * NE) return;
    int s, d;
    if (e < NE) {
        s = eh[e];
        d = eh[NE + e];
    } else {
        s = et[e - NE] + NN;
        d = et[NE + (e - NE)] + NN;
    }
    int p = atomicAdd(&g_cur[d], 1);
    g_srcs[p] = s;
}

__global__ void k_selfloops() {
    int i = blockIdx.x * blockDim.x + threadIdx.x;
    if (i >= NN2) return;
    int p = atomicAdd(&g_cur[i], 1);
    g_srcs[p] = i;
}

// ---------------- bf16x3 tensor-core GEMM + fused att-score epilogue ----------------
__device__ __forceinline__ void mma16816(float* c, const unsigned* a, const unsigned* b) {
    asm volatile(
        "mma.sync.aligned.m16n8k16.row.col.f32.bf16.bf16.f32 "
        "{%0,%1,%2,%3},{%4,%5,%6,%7},{%8,%9},{%0,%1,%2,%3};"
        : "+f"(c[0]), "+f"(c[1]), "+f"(c[2]), "+f"(c[3])
        : "r"(a[0]), "r"(a[1]), "r"(a[2]), "r"(a[3]), "r"(b[0]), "r"(b[1]));
}

#define LDP 40               // bf16 elems per smem row (80B pitch) -> conflict-free
#define ARR_B 10240          // bytes per array (128*40*2)
#define BUF_B 40960          // bytes per buffer (4 arrays)
#define GSMEM (2 * BUF_B)    // 80 KB

__device__ __forceinline__ void cp16(uint32_t dst, const void* src, bool pred) {
    asm volatile("cp.async.cg.shared.global [%0], [%1], 16, %2;"
                 :: "r"(dst), "l"(src), "r"(pred ? 16 : 0));
}

__global__ void __launch_bounds__(256, 2) k_gemm(const __nv_bfloat16* __restrict__ whi,
                                                 const __nv_bfloat16* __restrict__ wlo,
                                                 const float* __restrict__ a_s,
                                                 const float* __restrict__ a_d) {
    extern __shared__ __align__(16) unsigned char smem[];
    uint32_t smem_s = (uint32_t)__cvta_generic_to_shared(smem);
    int tid = threadIdx.x;
    int bx = blockIdx.x;
    int mBase = blockIdx.y * 128, nBase = bx * 128;
    int w = tid >> 5, lane = tid & 31;
    int wm = w >> 2, wn = w & 3;
    int g = lane >> 2, thr = lane & 3;
    float c[4][4][4];
#pragma unroll
    for (int a = 0; a < 4; a++)
#pragma unroll
        for (int b = 0; b < 4; b++)
#pragma unroll
            for (int d = 0; d < 4; d++) c[a][b][d] = 0.f;

    int i0 = tid, i1 = tid + 256;
    int r0c = i0 >> 2, ch0 = (i0 & 3) * 8;
    int r1c = i1 >> 2, ch1 = (i1 & 3) * 8;
    bool p0 = (mBase + r0c) < NN2, p1 = (mBase + r1c) < NN2;
    size_t aof0 = (size_t)(mBase + r0c) * ND + ch0;
    size_t aof1 = (size_t)(mBase + r1c) * ND + ch1;
    size_t bof0 = (size_t)(nBase + r0c) * ND + ch0;
    size_t bof1 = (size_t)(nBase + r1c) * ND + ch1;
    uint32_t d00 = smem_s + r0c * 80 + ch0 * 2;
    uint32_t d01 = smem_s + r1c * 80 + ch1 * 2;

    auto issue = [&](int t, int buf) {
        int k0 = t * 32;
        uint32_t bb = (uint32_t)buf * BUF_B;
        cp16(d00 + bb,             g_xhi + aof0 + k0, p0);
        cp16(d01 + bb,             g_xhi + aof1 + k0, p1);
        cp16(d00 + bb + ARR_B,     g_xlo + aof0 + k0, p0);
        cp16(d01 + bb + ARR_B,     g_xlo + aof1 + k0, p1);
        cp16(d00 + bb + 2 * ARR_B, whi + bof0 + k0, true);
        cp16(d01 + bb + 2 * ARR_B, whi + bof1 + k0, true);
        cp16(d00 + bb + 3 * ARR_B, wlo + bof0 + k0, true);
        cp16(d01 + bb + 3 * ARR_B, wlo + bof1 + k0, true);
        asm volatile("cp.async.commit_group;");
    };

    issue(0, 0);
    for (int t = 0; t < 8; t++) {
        if (t < 7) {
            issue(t + 1, (t + 1) & 1);
            asm volatile("cp.async.wait_group 1;");
        } else {
            asm volatile("cp.async.wait_group 0;");
        }
        __syncthreads();

        const __nv_bfloat16* Ah = (const __nv_bfloat16*)(smem + (t & 1) * BUF_B);
        const __nv_bfloat16* Al = Ah + 5120;
        const __nv_bfloat16* Bh = Ah + 10240;
        const __nv_bfloat16* Bl = Ah + 15360;

#pragma unroll
        for (int kk = 0; kk < 32; kk += 16) {
            unsigned bhf[4][2], blf[4][2];
#pragma unroll
            for (int ni = 0; ni < 4; ni++) {
                int nr = wn * 32 + ni * 8 + g;
                bhf[ni][0] = *(const unsigned*)&Bh[nr * LDP + kk + thr * 2];
                bhf[ni][1] = *(const unsigned*)&Bh[nr * LDP + kk + thr * 2 + 8];
                blf[ni][0] = *(const unsigned*)&Bl[nr * LDP + kk + thr * 2];
                blf[ni][1] = *(const unsigned*)&Bl[nr * LDP + kk + thr * 2 + 8];
            }
#pragma unroll
            for (int mi = 0; mi < 4; mi++) {
                int r0 = wm * 64 + mi * 16 + g;
                unsigned ahf[4], alf[4];
                ahf[0] = *(const unsigned*)&Ah[r0 * LDP + kk + thr * 2];
                ahf[1] = *(const unsigned*)&Ah[(r0 + 8) * LDP + kk + thr * 2];
                ahf[2] = *(const unsigned*)&Ah[r0 * LDP + kk + thr * 2 + 8];
                ahf[3] = *(const unsigned*)&Ah[(r0 + 8) * LDP + kk + thr * 2 + 8];
                alf[0] = *(const unsigned*)&Al[r0 * LDP + kk + thr * 2];
                alf[1] = *(const unsigned*)&Al[(r0 + 8) * LDP + kk + thr * 2];
                alf[2] = *(const unsigned*)&Al[r0 * LDP + kk + thr * 2 + 8];
                alf[3] = *(const unsigned*)&Al[(r0 + 8) * LDP + kk + thr * 2 + 8];
#pragma unroll
                for (int ni = 0; ni < 4; ni++) {
                    mma16816(c[mi][ni], ahf, bhf[ni]);
                    mma16816(c[mi][ni], ahf, blf[ni]);
                    mma16816(c[mi][ni], alf, bhf[ni]);
                }
            }
        }
        __syncthreads();
    }

    // ---- store h (fp16 gather plane) ----
#pragma unroll
    for (int mi = 0; mi < 4; mi++) {
        int row0 = mBase + wm * 64 + mi * 16 + g;
#pragma unroll
        for (int ni = 0; ni < 4; ni++) {
            int col = nBase + wn * 32 + ni * 8 + thr * 2;
            if (row0 < NN2)
                *(__half2*)&g_hf[(size_t)row0 * ND + col] =
                    __floats2half2_rn(c[mi][ni][0], c[mi][ni][1]);
            if (row0 + 8 < NN2)
                *(__half2*)&g_hf[(size_t)(row0 + 8) * ND + col] =
                    __floats2half2_rn(c[mi][ni][2], c[mi][ni][3]);
        }
    }

    // ---- fused attention-score epilogue (fp32 accumulators) ----
    float2 asv[4], adv[4];
#pragma unroll
    for (int ni = 0; ni < 4; ni++) {
        int col = nBase + wn * 32 + ni * 8 + thr * 2;
        asv[ni] = *(const float2*)&a_s[col];
        adv[ni] = *(const float2*)&a_d[col];
    }
    float ps[4][2], pd[4][2];
#pragma unroll
    for (int mi = 0; mi < 4; mi++) {
        ps[mi][0] = ps[mi][1] = pd[mi][0] = pd[mi][1] = 0.f;
#pragma unroll
        for (int ni = 0; ni < 4; ni++) {
            ps[mi][0] += c[mi][ni][0] * asv[ni].x + c[mi][ni][1] * asv[ni].y;
            ps[mi][1] += c[mi][ni][2] * asv[ni].x + c[mi][ni][3] * asv[ni].y;
            pd[mi][0] += c[mi][ni][0] * adv[ni].x + c[mi][ni][1] * adv[ni].y;
            pd[mi][1] += c[mi][ni][2] * adv[ni].x + c[mi][ni][3] * adv[ni].y;
        }
    }
#pragma unroll
    for (int off = 1; off < 4; off <<= 1) {
#pragma unroll
        for (int mi = 0; mi < 4; mi++) {
#pragma unroll
            for (int j = 0; j < 2; j++) {
                ps[mi][j] += __shfl_xor_sync(0xffffffffu, ps[mi][j], off);
                pd[mi][j] += __shfl_xor_sync(0xffffffffu, pd[mi][j], off);
            }
        }
    }
    float2* arr = (float2*)smem;   // [128 rows][4 wn] -> 4 KB
    if (thr == 0) {
#pragma unroll
        for (int mi = 0; mi < 4; mi++) {
#pragma unroll
            for (int j = 0; j < 2; j++) {
                int row = wm * 64 + mi * 16 + g + j * 8;
                arr[row * 4 + wn] = make_float2(ps[mi][j], pd[mi][j]);
            }
        }
    }
    __syncthreads();
    if (tid < 128) {
        int rg = mBase + tid;
        if (rg < NN2) {
            float2 q0 = arr[tid * 4 + 0], q1 = arr[tid * 4 + 1];
            float2 q2 = arr[tid * 4 + 2], q3 = arr[tid * 4 + 3];
            int hb = bx * 2;
            g_asrc[rg * 4 + hb]     = q0.x + q1.x;
            g_asrc[rg * 4 + hb + 1] = q2.x + q3.x;
            g_adst[rg * 4 + hb]     = q0.y + q1.y;
            g_adst[rg * 4 + hb + 1] = q2.y + q3.y;
        }
    }
}

// ---------------- aggregation: fused logits + segment softmax + fp16 gather + ELU ----------------
__global__ void __launch_bounds__(256) k_agg(const float* __restrict__ bias, int last) {
    int warp = threadIdx.x >> 5;
    int lane = threadIdx.x & 31;
    int node = blockIdx.x * 2 + (warp >> 2);
    int head = warp & 3;
    if (node >= NN2) return;
    int beg = g_off[node];
    int cnt_all = g_counts[node];
    int end = beg + cnt_all;
    float adst_n = g_adst[node * 4 + head];

    int c2 = head * HC + lane * 2;
    float accx = 0.f, accy = 0.f, denom = 0.f;

    if (cnt_all <= 32) {
        bool ok = lane < cnt_all;
        int s = ok ? g_srcs[beg + lane] : 0;
        float a = -1e30f;
        if (ok) {
            a = g_asrc[s * 4 + head] + adst_n;
            a = a > 0.f ? a : 0.2f * a;
        }
        float m = a;
#pragma unroll
        for (int o = 16; o; o >>= 1) m = fmaxf(m, __shfl_xor_sync(0xffffffffu, m, o));
        float ea = ok ? __expf(a - m) : 0.f;
        denom = ea;
        for (int j = 0; j < cnt_all; j++) {
            float eaj = __shfl_sync(0xffffffffu, ea, j);
            int sj = __shfl_sync(0xffffffffu, s, j);
            float2 hv = __half22float2(*(const __half2*)(g_hf + (size_t)sj * ND + c2));
            accx += eaj * hv.x;
            accy += eaj * hv.y;
        }
    } else {
        float m = -1e30f;
        for (int i = beg + lane; i < end; i += 32) {
            int s = g_srcs[i];
            float a = g_asrc[s * 4 + head] + adst_n;
            a = a > 0.f ? a : 0.2f * a;
            m = fmaxf(m, a);
        }
#pragma unroll
        for (int o = 16; o; o >>= 1) m = fmaxf(m, __shfl_xor_sync(0xffffffffu, m, o));
        for (int base = beg; base < end; base += 32) {
            int i = base + lane;
            float ea = 0.f;
            int s = 0;
            if (i < end) {
                s = g_srcs[i];
                float a = g_asrc[s * 4 + head] + adst_n;
                a = a > 0.f ? a : 0.2f * a;
                ea = __expf(a - m);
            }
            denom += ea;
            int cnt = min(32, end - base);
            for (int j = 0; j < cnt; j++) {
                float eaj = __shfl_sync(0xffffffffu, ea, j);
                int sj = __shfl_sync(0xffffffffu, s, j);
                float2 hv = __half22float2(*(const __half2*)(g_hf + (size_t)sj * ND + c2));
                accx += eaj * hv.x;
                accy += eaj * hv.y;
            }
        }
    }
#pragma unroll
    for (int o = 16; o; o >>= 1) denom += __shfl_xor_sync(0xffffffffu, denom, o);

    float inv = 1.0f / denom;
    float v0 = accx * inv + bias[c2];
    float v1 = accy * inv + bias[c2 + 1];
    v0 = v0 > 0.f ? v0 : expm1f(v0);
    v1 = v1 > 0.f ? v1 : expm1f(v1);

    size_t o0 = (size_t)node * ND + c2;
    __nv_bfloat16 h0, l0, h1, l1;
    split_bf16(v0, h0, l0);
    split_bf16(v1, h1, l1);
    *(__nv_bfloat162*)(g_xhi + o0) = __nv_bfloat162(h0, h1);
    *(__nv_bfloat162*)(g_xlo + o0) = __nv_bfloat162(l0, l1);
    if (last) *(float2*)(g_x + o0) = make_float2(v0, v1);
}

// ---------------- pooling (both encoders, 1024 blocks) ----------------
__global__ void k_pool(const int* __restrict__ hb, const int* __restrict__ tb) {
    __shared__ int sb, se;
    int b = blockIdx.x;
    int which = b >= NB;
    int bb = which ? b - NB : b;
    const int* batch = which ? tb : hb;
    if (threadIdx.x == 0) {
        int lo = 0, hi = NN;
        while (lo < hi) { int mid = (lo + hi) >> 1; if (batch[mid] < bb) lo = mid + 1; else hi = mid; }
        sb = lo;
        lo = 0; hi = NN;
        while (lo < hi) { int mid = (lo + hi) >> 1; if (batch[mid] < bb + 1) lo = mid + 1; else hi = mid; }
        se = lo;
    }
    __syncthreads();
    int c = threadIdx.x;
    int base = which ? NN : 0;
    float acc = 0.f;
    for (int i = sb; i < se; i++) acc += g_x[(size_t)(base + i) * ND + c];
    (which ? g_te : g_he)[bb * ND + c] = acc;
}

// ---------------- final MLP ----------------
__global__ void k_mlp(const int* __restrict__ rel, const float* __restrict__ kge,
                      const float* __restrict__ W1, const float* __restrict__ b1,
                      const float* __restrict__ W2, const float* __restrict__ b2,
                      float* __restrict__ out) {
    int b = blockIdx.x;
    int j = threadIdx.x;
    __shared__ float zin[2 * ND + HC];
    for (int k = j; k < ND; k += 64) zin[k] = g_he[b * ND + k];
    for (int k = j; k < ND; k += 64) zin[ND + k] = g_te[b * ND + k];
    int r = rel[b];
    zin[2 * ND + j] = kge[r * HC + j];
    __syncthreads();
    float z = b1[j];
    for (int k = 0; k < 2 * ND + HC; k++) z += zin[k] * W1[k * 64 + j];
    z = fmaxf(z, 0.f);
    __shared__ float zs[64];
    zs[j] = z * W2[j];
    __syncthreads();
    if (j < 32) {
        float v = zs[j] + zs[j + 32];
#pragma unroll
        for (int o = 16; o; o >>= 1) v += __shfl_xor_sync(0xffffffffu, v, o);
        if (j == 0) out[b] = v + b2[0];
    }
}

// ---------------- launcher ----------------
extern "C" void kernel_launch(void* const* d_in, const int* in_sizes, int n_in,
                              void* d_out, int out_size) {
    const float* head_x    = (const float*)d_in[0];
    const int*   head_ei   = (const int*)d_in[1];
    const int*   head_b    = (const int*)d_in[2];
    const float* tail_x    = (const float*)d_in[3];
    const int*   tail_ei   = (const int*)d_in[4];
    const int*   tail_b    = (const int*)d_in[5];
    const int*   rel       = (const int*)d_in[6];
    const float* Ws        = (const float*)d_in[7];
    const float* att_src   = (const float*)d_in[8];
    const float* att_dst   = (const float*)d_in[9];
    const float* biases    = (const float*)d_in[10];
    const float* kge       = (const float*)d_in[11];
    const float* W1        = (const float*)d_in[12];
    const float* b1        = (const float*)d_in[13];
    const float* W2        = (const float*)d_in[14];
    const float* b2        = (const float*)d_in[15];
    float*       out       = (float*)d_out;

    cudaFuncSetAttribute(k_gemm, cudaFuncAttributeMaxDynamicSharedMemorySize, GSMEM);

    const int TB = 256;
    __nv_bfloat16 *whi0, *wlo0;
    cudaGetSymbolAddress((void**)&whi0, g_whi);
    cudaGetSymbolAddress((void**)&wlo0, g_wlo);

    k_split_w<<<(3 * ND * ND + TB - 1) / TB, TB>>>(Ws);
    k_init_counts<<<(NN2 + TB - 1) / TB, TB>>>();
    k_count<<<(2 * NE + TB - 1) / TB, TB>>>(head_ei, tail_ei);
    k_assign<<<(NN2 + TB - 1) / TB, TB>>>();
    k_scatter<<<(2 * NE + TB - 1) / TB, TB>>>(head_ei, tail_ei);
    k_selfloops<<<(NN2 + TB - 1) / TB, TB>>>();
    k_split_x<<<1184, 256>>>(head_x, tail_x);

    for (int l = 0; l < 3; l++) {
        k_gemm<<<dim3(2, (NN2 + 127) / 128), 256, GSMEM>>>(
            whi0 + (size_t)l * ND * ND, wlo0 + (size_t)l * ND * ND,
            att_src + l * ND, att_dst + l * ND);
        k_agg<<<NN2 / 2, 256>>>(biases + l * ND, l == 2);
    }
    k_pool<<<2 * NB, ND>>>(head_b, tail_b);
    k_mlp<<<NB, 64>>>(rel, kge, W1, b1, W2, b2, out);
}

// round 11
// speedup vs baseline: 2.0777x; 1.0384x over previous
#include <cuda_runtime.h>
#include <cuda_bf16.h>
#include <cuda_fp16.h>
#include <stdint.h>
#include <math.h>

#define NN 50000
#define NN2 (2 * NN)
#define NE 800000
#define ET2 (2 * (NN + NE))
#define NB 512
#define ND 256
#define NH 4
#define HC 64

// ---------------- static device scratch ----------------
__device__ float g_x[(size_t)NN2 * ND];
__device__ __nv_bfloat16 g_xhi[(size_t)NN2 * ND];
__device__ __nv_bfloat16 g_xlo[(size_t)NN2 * ND];
__device__ __nv_bfloat16 g_whi[3 * ND * ND];   // transposed [l][n][k]
__device__ __nv_bfloat16 g_wlo[3 * ND * ND];
__device__ __half g_hf[(size_t)NN2 * ND];      // h in fp16 (gather plane)
__device__ float g_asrc[NN2 * NH];
__device__ float g_adst[NN2 * NH];
__device__ int   g_counts[NN2];
__device__ int   g_off[NN2];
__device__ int   g_cur[NN2];
__device__ int   g_srcs[ET2];
__device__ int   g_total;
__device__ float g_he[NB * ND];
__device__ float g_te[NB * ND];

// ---------------- fp32 -> bf16 hi/lo split ----------------
__device__ __forceinline__ void split_bf16(float v, __nv_bfloat16& hi, __nv_bfloat16& lo) {
    hi = __float2bfloat16(v);
    lo = __float2bfloat16(v - __bfloat162float(hi));
}

// vectorized: 4 floats/thread, 8B stores
__global__ void k_split_x(const float* __restrict__ xh, const float* __restrict__ xt) {
    const int n4 = NN2 * ND / 4;
    const int h4 = NN * ND / 4;
    int i = blockIdx.x * blockDim.x + threadIdx.x;
    int stride = gridDim.x * blockDim.x;
    for (; i < n4; i += stride) {
        float4 v = (i < h4) ? ((const float4*)xh)[i] : ((const float4*)xt)[i - h4];
        __nv_bfloat16 h0, l0, h1, l1, h2, l2, h3, l3;
        split_bf16(v.x, h0, l0);
        split_bf16(v.y, h1, l1);
        split_bf16(v.z, h2, l2);
        split_bf16(v.w, h3, l3);
        __nv_bfloat162 hv0(h0, h1), hv1(h2, h3), lv0(l0, l1), lv1(l2, l3);
        uint2 hp, lp;
        hp.x = *(unsigned*)&hv0; hp.y = *(unsigned*)&hv1;
        lp.x = *(unsigned*)&lv0; lp.y = *(unsigned*)&lv1;
        ((uint2*)g_xhi)[i] = hp;
        ((uint2*)g_xlo)[i] = lp;
    }
}

__global__ void k_split_w(const float* __restrict__ Ws) {
    int i = blockIdx.x * blockDim.x + threadIdx.x;
    if (i >= 3 * ND * ND) return;
    int l = i / (ND * ND);
    int r = i % (ND * ND);
    int n = r / ND;
    int k = r % ND;
    float v = Ws[l * ND * ND + k * ND + n];
    __nv_bfloat16 hi, lo;
    split_bf16(v, hi, lo);
    g_whi[i] = hi;
    g_wlo[i] = lo;
}

// ---------------- merged CSR construction ----------------
__global__ void k_init_counts() {
    int i = blockIdx.x * blockDim.x + threadIdx.x;
    if (i < NN2) g_counts[i] = 1;   // self-loop pre-counted
    if (i == 0) g_total = 0;
}

__global__ void k_count(const int* __restrict__ eh, const int* __restrict__ et) {
    int e = blockIdx.x * blockDim.x + threadIdx.x;
    if (e >= 2 * NE) return;
    int d = (e < NE) ? eh[NE + e] : (et[NE + (e - NE)] + NN);
    atomicAdd(&g_counts[d], 1);
}

__global__ void k_assign() {
    int i = blockIdx.x * blockDim.x + threadIdx.x;
    int lane = threadIdx.x & 31;
    int v = (i < NN2) ? g_counts[i] : 0;
    int inc = v;
#pragma unroll
    for (int o = 1; o < 32; o <<= 1) {
        int t = __shfl_up_sync(0xffffffffu, inc, o);
        if (lane >= o) inc += t;
    }
    int wtot = __shfl_sync(0xffffffffu, inc, 31);
    int base = 0;
    if (lane == 31) base = atomicAdd(&g_total, wtot);
    base = __shfl_sync(0xffffffffu, base, 31);
    if (i < NN2) {
        int p = base + inc - v;
        g_off[i] = p;
        g_cur[i] = p;
    }
}

__global__ void k_scatter(const int* __restrict__ eh, const int* __restrict__ et) {
    int e = blockIdx.x * blockDim.x + threadIdx.x;
    if (e >= 2 * NE) return;
    int s, d;
    if (e < NE) {
        s = eh[e];
        d = eh[NE + e];
    } else {
        s = et[e - NE] + NN;
        d = et[NE + (e - NE)] + NN;
    }
    int p = atomicAdd(&g_cur[d], 1);
    g_srcs[p] = s;
}

__global__ void k_selfloops() {
    int i = blockIdx.x * blockDim.x + threadIdx.x;
    if (i >= NN2) return;
    int p = atomicAdd(&g_cur[i], 1);
    g_srcs[p] = i;
}

// ---------------- bf16x3 tensor-core GEMM + fused att-score epilogue ----------------
__device__ __forceinline__ void mma16816(float* c, const unsigned* a, const unsigned* b) {
    asm volatile(
        "mma.sync.aligned.m16n8k16.row.col.f32.bf16.bf16.f32 "
        "{%0,%1,%2,%3},{%4,%5,%6,%7},{%8,%9},{%0,%1,%2,%3};"
        : "+f"(c[0]), "+f"(c[1]), "+f"(c[2]), "+f"(c[3])
        : "r"(a[0]), "r"(a[1]), "r"(a[2]), "r"(a[3]), "r"(b[0]), "r"(b[1]));
}

#define LDP 40
#define ARR_B 10240
#define BUF_B 40960
#define GSMEM (2 * BUF_B)

__device__ __forceinline__ void cp16(uint32_t dst, const void* src, bool pred) {
    asm volatile("cp.async.cg.shared.global [%0], [%1], 16, %2;"
                 :: "r"(dst), "l"(src), "r"(pred ? 16 : 0));
}

__global__ void __launch_bounds__(256, 2) k_gemm(const __nv_bfloat16* __restrict__ whi,
                                                 const __nv_bfloat16* __restrict__ wlo,
                                                 const float* __restrict__ a_s,
                                                 const float* __restrict__ a_d) {
    extern __shared__ __align__(16) unsigned char smem[];
    uint32_t smem_s = (uint32_t)__cvta_generic_to_shared(smem);
    int tid = threadIdx.x;
    int bx = blockIdx.x;
    int mBase = blockIdx.y * 128, nBase = bx * 128;
    int w = tid >> 5, lane = tid & 31;
    int wm = w >> 2, wn = w & 3;
    int g = lane >> 2, thr = lane & 3;
    float c[4][4][4];
#pragma unroll
    for (int a = 0; a < 4; a++)
#pragma unroll
        for (int b = 0; b < 4; b++)
#pragma unroll
            for (int d = 0; d < 4; d++) c[a][b][d] = 0.f;

    int i0 = tid, i1 = tid + 256;
    int r0c = i0 >> 2, ch0 = (i0 & 3) * 8;
    int r1c = i1 >> 2, ch1 = (i1 & 3) * 8;
    bool p0 = (mBase + r0c) < NN2, p1 = (mBase + r1c) < NN2;
    size_t aof0 = (size_t)(mBase + r0c) * ND + ch0;
    size_t aof1 = (size_t)(mBase + r1c) * ND + ch1;
    size_t bof0 = (size_t)(nBase + r0c) * ND + ch0;
    size_t bof1 = (size_t)(nBase + r1c) * ND + ch1;
    uint32_t d00 = smem_s + r0c * 80 + ch0 * 2;
    uint32_t d01 = smem_s + r1c * 80 + ch1 * 2;

    auto issue = [&](int t, int buf) {
        int k0 = t * 32;
        uint32_t bb = (uint32_t)buf * BUF_B;
        cp16(d00 + bb,             g_xhi + aof0 + k0, p0);
        cp16(d01 + bb,             g_xhi + aof1 + k0, p1);
        cp16(d00 + bb + ARR_B,     g_xlo + aof0 + k0, p0);
        cp16(d01 + bb + ARR_B,     g_xlo + aof1 + k0, p1);
        cp16(d00 + bb + 2 * ARR_B, whi + bof0 + k0, true);
        cp16(d01 + bb + 2 * ARR_B, whi + bof1 + k0, true);
        cp16(d00 + bb + 3 * ARR_B, wlo + bof0 + k0, true);
        cp16(d01 + bb + 3 * ARR_B, wlo + bof1 + k0, true);
        asm volatile("cp.async.commit_group;");
    };

    issue(0, 0);
    for (int t = 0; t < 8; t++) {
        if (t < 7) {
            issue(t + 1, (t + 1) & 1);
            asm volatile("cp.async.wait_group 1;");
        } else {
            asm volatile("cp.async.wait_group 0;");
        }
        __syncthreads();

        const __nv_bfloat16* Ah = (const __nv_bfloat16*)(smem + (t & 1) * BUF_B);
        const __nv_bfloat16* Al = Ah + 5120;
        const __nv_bfloat16* Bh = Ah + 10240;
        const __nv_bfloat16* Bl = Ah + 15360;

#pragma unroll
        for (int kk = 0; kk < 32; kk += 16) {
            unsigned bhf[4][2], blf[4][2];
#pragma unroll
            for (int ni = 0; ni < 4; ni++) {
                int nr = wn * 32 + ni * 8 + g;
                bhf[ni][0] = *(const unsigned*)&Bh[nr * LDP + kk + thr * 2];
                bhf[ni][1] = *(const unsigned*)&Bh[nr * LDP + kk + thr * 2 + 8];
                blf[ni][0] = *(const unsigned*)&Bl[nr * LDP + kk + thr * 2];
                blf[ni][1] = *(const unsigned*)&Bl[nr * LDP + kk + thr * 2 + 8];
            }
#pragma unroll
            for (int mi = 0; mi < 4; mi++) {
                int r0 = wm * 64 + mi * 16 + g;
                unsigned ahf[4], alf[4];
                ahf[0] = *(const unsigned*)&Ah[r0 * LDP + kk + thr * 2];
                ahf[1] = *(const unsigned*)&Ah[(r0 + 8) * LDP + kk + thr * 2];
                ahf[2] = *(const unsigned*)&Ah[r0 * LDP + kk + thr * 2 + 8];
                ahf[3] = *(const unsigned*)&Ah[(r0 + 8) * LDP + kk + thr * 2 + 8];
                alf[0] = *(const unsigned*)&Al[r0 * LDP + kk + thr * 2];
                alf[1] = *(const unsigned*)&Al[(r0 + 8) * LDP + kk + thr * 2];
                alf[2] = *(const unsigned*)&Al[r0 * LDP + kk + thr * 2 + 8];
                alf[3] = *(const unsigned*)&Al[(r0 + 8) * LDP + kk + thr * 2 + 8];
#pragma unroll
                for (int ni = 0; ni < 4; ni++) {
                    mma16816(c[mi][ni], ahf, bhf[ni]);
                    mma16816(c[mi][ni], ahf, blf[ni]);
                    mma16816(c[mi][ni], alf, bhf[ni]);
                }
            }
        }
        __syncthreads();
    }

    // ---- store h (fp16 gather plane) ----
#pragma unroll
    for (int mi = 0; mi < 4; mi++) {
        int row0 = mBase + wm * 64 + mi * 16 + g;
#pragma unroll
        for (int ni = 0; ni < 4; ni++) {
            int col = nBase + wn * 32 + ni * 8 + thr * 2;
            if (row0 < NN2)
                *(__half2*)&g_hf[(size_t)row0 * ND + col] =
                    __floats2half2_rn(c[mi][ni][0], c[mi][ni][1]);
            if (row0 + 8 < NN2)
                *(__half2*)&g_hf[(size_t)(row0 + 8) * ND + col] =
                    __floats2half2_rn(c[mi][ni][2], c[mi][ni][3]);
        }
    }

    // ---- fused attention-score epilogue ----
    float2 asv[4], adv[4];
#pragma unroll
    for (int ni = 0; ni < 4; ni++) {
        int col = nBase + wn * 32 + ni * 8 + thr * 2;
        asv[ni] = *(const float2*)&a_s[col];
        adv[ni] = *(const float2*)&a_d[col];
    }
    float ps[4][2], pd[4][2];
#pragma unroll
    for (int mi = 0; mi < 4; mi++) {
        ps[mi][0] = ps[mi][1] = pd[mi][0] = pd[mi][1] = 0.f;
#pragma unroll
        for (int ni = 0; ni < 4; ni++) {
            ps[mi][0] += c[mi][ni][0] * asv[ni].x + c[mi][ni][1] * asv[ni].y;
            ps[mi][1] += c[mi][ni][2] * asv[ni].x + c[mi][ni][3] * asv[ni].y;
            pd[mi][0] += c[mi][ni][0] * adv[ni].x + c[mi][ni][1] * adv[ni].y;
            pd[mi][1] += c[mi][ni][2] * adv[ni].x + c[mi][ni][3] * adv[ni].y;
        }
    }
#pragma unroll
    for (int off = 1; off < 4; off <<= 1) {
#pragma unroll
        for (int mi = 0; mi < 4; mi++) {
#pragma unroll
            for (int j = 0; j < 2; j++) {
                ps[mi][j] += __shfl_xor_sync(0xffffffffu, ps[mi][j], off);
                pd[mi][j] += __shfl_xor_sync(0xffffffffu, pd[mi][j], off);
            }
        }
    }
    float2* arr = (float2*)smem;
    if (thr == 0) {
#pragma unroll
        for (int mi = 0; mi < 4; mi++) {
#pragma unroll
            for (int j = 0; j < 2; j++) {
                int row = wm * 64 + mi * 16 + g + j * 8;
                arr[row * 4 + wn] = make_float2(ps[mi][j], pd[mi][j]);
            }
        }
    }
    __syncthreads();
    if (tid < 128) {
        int rg = mBase + tid;
        if (rg < NN2) {
            float2 q0 = arr[tid * 4 + 0], q1 = arr[tid * 4 + 1];
            float2 q2 = arr[tid * 4 + 2], q3 = arr[tid * 4 + 3];
            int hb = bx * 2;
            g_asrc[rg * 4 + hb]     = q0.x + q1.x;
            g_asrc[rg * 4 + hb + 1] = q2.x + q3.x;
            g_adst[rg * 4 + hb]     = q0.y + q1.y;
            g_adst[rg * 4 + hb + 1] = q2.y + q3.y;
        }
    }
}

// ---------------- aggregation: fused logits + softmax + fp16 gather (x4 unrolled) ----------------
__global__ void __launch_bounds__(256) k_agg(const float* __restrict__ bias, int last) {
    int warp = threadIdx.x >> 5;
    int lane = threadIdx.x & 31;
    int node = blockIdx.x * 2 + (warp >> 2);
    int head = warp & 3;
    if (node >= NN2) return;
    int beg = g_off[node];
    int cnt_all = g_counts[node];
    int end = beg + cnt_all;
    float adst_n = g_adst[node * 4 + head];

    int c2 = head * HC + lane * 2;
    const __half* hf = g_hf + c2;
    float accx = 0.f, accy = 0.f, denom = 0.f;

    auto bcast4 = [&](float ea, int s, int j) {
        float e0 = __shfl_sync(0xffffffffu, ea, j);
        float e1 = __shfl_sync(0xffffffffu, ea, j + 1);
        float e2 = __shfl_sync(0xffffffffu, ea, j + 2);
        float e3 = __shfl_sync(0xffffffffu, ea, j + 3);
        int s0 = __shfl_sync(0xffffffffu, s, j);
        int s1 = __shfl_sync(0xffffffffu, s, j + 1);
        int s2 = __shfl_sync(0xffffffffu, s, j + 2);
        int s3 = __shfl_sync(0xffffffffu, s, j + 3);
        float2 h0 = __half22float2(*(const __half2*)(hf + (size_t)s0 * ND));
        float2 h1 = __half22float2(*(const __half2*)(hf + (size_t)s1 * ND));
        float2 h2 = __half22float2(*(const __half2*)(hf + (size_t)s2 * ND));
        float2 h3 = __half22float2(*(const __half2*)(hf + (size_t)s3 * ND));
        accx += e0 * h0.x + e1 * h1.x + e2 * h2.x + e3 * h3.x;
        accy += e0 * h0.y + e1 * h1.y + e2 * h2.y + e3 * h3.y;
    };
    auto bcast1 = [&](float ea, int s, int j) {
        float e0 = __shfl_sync(0xffffffffu, ea, j);
        int s0 = __shfl_sync(0xffffffffu, s, j);
        float2 h0 = __half22float2(*(const __half2*)(hf + (size_t)s0 * ND));
        accx += e0 * h0.x;
        accy += e0 * h0.y;
    };

    if (cnt_all <= 32) {
        bool ok = lane < cnt_all;
        int s = ok ? g_srcs[beg + lane] : 0;
        float a = -1e30f;
        if (ok) {
            a = g_asrc[s * 4 + head] + adst_n;
            a = a > 0.f ? a : 0.2f * a;
        }
        float m = a;
#pragma unroll
        for (int o = 16; o; o >>= 1) m = fmaxf(m, __shfl_xor_sync(0xffffffffu, m, o));
        float ea = ok ? __expf(a - m) : 0.f;
        denom = ea;
        int j = 0;
        for (; j + 4 <= cnt_all; j += 4) bcast4(ea, s, j);
        for (; j < cnt_all; j++) bcast1(ea, s, j);
    } else {
        float m = -1e30f;
        for (int i = beg + lane; i < end; i += 32) {
            int s = g_srcs[i];
            float a = g_asrc[s * 4 + head] + adst_n;
            a = a > 0.f ? a : 0.2f * a;
            m = fmaxf(m, a);
        }
#pragma unroll
        for (int o = 16; o; o >>= 1) m = fmaxf(m, __shfl_xor_sync(0xffffffffu, m, o));
        for (int base = beg; base < end; base += 32) {
            int i = base + lane;
            float ea = 0.f;
            int s = 0;
            if (i < end) {
                s = g_srcs[i];
                float a = g_asrc[s * 4 + head] + adst_n;
                a = a > 0.f ? a : 0.2f * a;
                ea = __expf(a - m);
            }
            denom += ea;
            int cnt = min(32, end - base);
            int j = 0;
            for (; j + 4 <= cnt; j += 4) bcast4(ea, s, j);
            for (; j < cnt; j++) bcast1(ea, s, j);
        }
    }
#pragma unroll
    for (int o = 16; o; o >>= 1) denom += __shfl_xor_sync(0xffffffffu, denom, o);

    float inv = 1.0f / denom;
    float v0 = accx * inv + bias[c2];
    float v1 = accy * inv + bias[c2 + 1];
    v0 = v0 > 0.f ? v0 : expm1f(v0);
    v1 = v1 > 0.f ? v1 : expm1f(v1);

    size_t o0 = (size_t)node * ND + c2;
    __nv_bfloat16 h0, l0, h1, l1;
    split_bf16(v0, h0, l0);
    split_bf16(v1, h1, l1);
    *(__nv_bfloat162*)(g_xhi + o0) = __nv_bfloat162(h0, h1);
    *(__nv_bfloat162*)(g_xlo + o0) = __nv_bfloat162(l0, l1);
    if (last) *(float2*)(g_x + o0) = make_float2(v0, v1);
}

// ---------------- pooling ----------------
__global__ void k_pool(const int* __restrict__ hb, const int* __restrict__ tb) {
    __shared__ int sb, se;
    int b = blockIdx.x;
    int which = b >= NB;
    int bb = which ? b - NB : b;
    const int* batch = which ? tb : hb;
    if (threadIdx.x == 0) {
        int lo = 0, hi = NN;
        while (lo < hi) { int mid = (lo + hi) >> 1; if (batch[mid] < bb) lo = mid + 1; else hi = mid; }
        sb = lo;
        lo = 0; hi = NN;
        while (lo < hi) { int mid = (lo + hi) >> 1; if (batch[mid] < bb + 1) lo = mid + 1; else hi = mid; }
        se = lo;
    }
    __syncthreads();
    int c = threadIdx.x;
    int base = which ? NN : 0;
    float acc = 0.f;
    for (int i = sb; i < se; i++) acc += g_x[(size_t)(base + i) * ND + c];
    (which ? g_te : g_he)[bb * ND + c] = acc;
}

// ---------------- final MLP ----------------
__global__ void k_mlp(const int* __restrict__ rel, const float* __restrict__ kge,
                      const float* __restrict__ W1, const float* __restrict__ b1,
                      const float* __restrict__ W2, const float* __restrict__ b2,
                      float* __restrict__ out) {
    int b = blockIdx.x;
    int j = threadIdx.x;
    __shared__ float zin[2 * ND + HC];
    for (int k = j; k < ND; k += 64) zin[k] = g_he[b * ND + k];
    for (int k = j; k < ND; k += 64) zin[ND + k] = g_te[b * ND + k];
    int r = rel[b];
    zin[2 * ND + j] = kge[r * HC + j];
    __syncthreads();
    float z = b1[j];
    for (int k = 0; k < 2 * ND + HC; k++) z += zin[k] * W1[k * 64 + j];
    z = fmaxf(z, 0.f);
    __shared__ float zs[64];
    zs[j] = z * W2[j];
    __syncthreads();
    if (j < 32) {
        float v = zs[j] + zs[j + 32];
#pragma unroll
        for (int o = 16; o; o >>= 1) v += __shfl_xor_sync(0xffffffffu, v, o);
        if (j == 0) out[b] = v + b2[0];
    }
}

// ---------------- launcher ----------------
extern "C" void kernel_launch(void* const* d_in, const int* in_sizes, int n_in,
                              void* d_out, int out_size) {
    const float* head_x    = (const float*)d_in[0];
    const int*   head_ei   = (const int*)d_in[1];
    const int*   head_b    = (const int*)d_in[2];
    const float* tail_x    = (const float*)d_in[3];
    const int*   tail_ei   = (const int*)d_in[4];
    const int*   tail_b    = (const int*)d_in[5];
    const int*   rel       = (const int*)d_in[6];
    const float* Ws        = (const float*)d_in[7];
    const float* att_src   = (const float*)d_in[8];
    const float* att_dst   = (const float*)d_in[9];
    const float* biases    = (const float*)d_in[10];
    const float* kge       = (const float*)d_in[11];
    const float* W1        = (const float*)d_in[12];
    const float* b1        = (const float*)d_in[13];
    const float* W2        = (const float*)d_in[14];
    const float* b2        = (const float*)d_in[15];
    float*       out       = (float*)d_out;

    static cudaStream_t s2 = nullptr;
    static cudaEvent_t evF = nullptr, evJ = nullptr;
    if (!s2) {
        cudaStreamCreateWithFlags(&s2, cudaStreamNonBlocking);
        cudaEventCreateWithFlags(&evF, cudaEventDisableTiming);
        cudaEventCreateWithFlags(&evJ, cudaEventDisableTiming);
    }

    cudaFuncSetAttribute(k_gemm, cudaFuncAttributeMaxDynamicSharedMemorySize, GSMEM);

    const int TB = 256;
    __nv_bfloat16 *whi0, *wlo0;
    cudaGetSymbolAddress((void**)&whi0, g_whi);
    cudaGetSymbolAddress((void**)&wlo0, g_wlo);

    // ---- fork: CSR build on s2, concurrent with split+GEMM0 on capture stream ----
    cudaEventRecord(evF, 0);
    cudaStreamWaitEvent(s2, evF, 0);
    k_init_counts<<<(NN2 + TB - 1) / TB, TB, 0, s2>>>();
    k_count<<<(2 * NE + TB - 1) / TB, TB, 0, s2>>>(head_ei, tail_ei);
    k_assign<<<(NN2 + TB - 1) / TB, TB, 0, s2>>>();
    k_scatter<<<(2 * NE + TB - 1) / TB, TB, 0, s2>>>(head_ei, tail_ei);
    k_selfloops<<<(NN2 + TB - 1) / TB, TB, 0, s2>>>();
    cudaEventRecord(evJ, s2);

    k_split_w<<<(3 * ND * ND + TB - 1) / TB, TB>>>(Ws);
    k_split_x<<<1184, 256>>>(head_x, tail_x);

    for (int l = 0; l < 3; l++) {
        k_gemm<<<dim3(2, (NN2 + 127) / 128), 256, GSMEM>>>(
            whi0 + (size_t)l * ND * ND, wlo0 + (size_t)l * ND * ND,
            att_src + l * ND, att_dst + l * ND);
        if (l == 0) cudaStreamWaitEvent(0, evJ, 0);   // join before first agg
        k_agg<<<NN2 / 2, 256>>>(biases + l * ND, l == 2);
    }
    k_pool<<<2 * NB, ND>>>(head_b, tail_b);
    k_mlp<<<NB, 64>>>(rel, kge, W1, b1, W2, b2, out);
}